// round 1
// baseline (speedup 1.0000x reference)
#include <cuda_runtime.h>
#include <cstdint>

#define NN 100000
#define EE 1600000
// feature dim = 128, classes = 40

// ---------------- scratch (static device allocations) ----------------
__device__ __align__(16) float g_agg0[NN * 128];
__device__ __align__(16) float g_agg1[NN * 128];
__device__ __align__(16) float g_agga2[NN * 128];
__device__ __align__(16) float g_aggb[NN * 128];
__device__ __align__(16) float g_h1[NN * 128];
__device__ __align__(16) float g_h2[NN * 128];
__device__ __align__(16) float g_z[NN * 128];
__device__ __align__(16) float g_mix0[NN * 128];
__device__ __align__(16) float g_mix1[NN * 128];

__device__ int g_cnt[NN];
__device__ int g_rpa[NN + 1];
__device__ int g_rpb[NN + 1];
__device__ int g_cur[NN];
__device__ int g_cola[EE];
__device__ int g_colb[EE];

// ---------------- helpers ----------------
__device__ __forceinline__ float2 ffma2(float2 a, float2 b, float2 c) {
    unsigned long long au = *reinterpret_cast<unsigned long long*>(&a);
    unsigned long long bu = *reinterpret_cast<unsigned long long*>(&b);
    unsigned long long cu = *reinterpret_cast<unsigned long long*>(&c);
    unsigned long long du;
    asm("fma.rn.f32x2 %0, %1, %2, %3;" : "=l"(du) : "l"(au), "l"(bu), "l"(cu));
    return *reinterpret_cast<float2*>(&du);
}

// ---------------- CSR build ----------------
__global__ void k_count(const int* __restrict__ dst, int* __restrict__ cnt, int E) {
    int i = blockIdx.x * blockDim.x + threadIdx.x;
    if (i < E) atomicAdd(&cnt[dst[i]], 1);
}

__global__ void k_scan(const int* __restrict__ cnt, int* __restrict__ rowptr, int n) {
    __shared__ int part[1024];
    int tid = threadIdx.x;
    int chunk = (n + 1023) >> 10;
    int s0 = tid * chunk;
    int s1 = min(s0 + chunk, n);
    int s = 0;
    for (int i = s0; i < s1; i++) s += cnt[i];
    part[tid] = s;
    __syncthreads();
    for (int off = 1; off < 1024; off <<= 1) {
        int v = part[tid];
        int u = (tid >= off) ? part[tid - off] : 0;
        __syncthreads();
        part[tid] = v + u;
        __syncthreads();
    }
    int run = (tid == 0) ? 0 : part[tid - 1];
    for (int i = s0; i < s1; i++) { rowptr[i] = run; run += cnt[i]; }
    if (tid == 1023) rowptr[n] = part[1023];
}

__global__ void k_fill(const int* __restrict__ src, const int* __restrict__ dst,
                       int* __restrict__ cursor, int* __restrict__ col,
                       const int* __restrict__ perm, int E) {
    int i = blockIdx.x * blockDim.x + threadIdx.x;
    if (i < E) {
        int d = dst[i];
        int pos = atomicAdd(&cursor[d], 1);
        int s = src[i];
        col[pos] = perm ? perm[s] : s;
    }
}

// ---------------- mean aggregation: one warp per node ----------------
__global__ void k_agg(const float4* __restrict__ feat, const int* __restrict__ rowptr,
                      const int* __restrict__ col, float4* __restrict__ out, int n) {
    int w = (blockIdx.x * blockDim.x + threadIdx.x) >> 5;
    int lane = threadIdx.x & 31;
    if (w >= n) return;
    int s = rowptr[w], e = rowptr[w + 1];
    float ax = 0.f, ay = 0.f, az = 0.f, aw = 0.f;
    int i = s;
    for (; i + 3 < e; i += 4) {
        int c0 = __ldg(&col[i + 0]);
        int c1 = __ldg(&col[i + 1]);
        int c2 = __ldg(&col[i + 2]);
        int c3 = __ldg(&col[i + 3]);
        float4 v0 = __ldg(&feat[c0 * 32 + lane]);
        float4 v1 = __ldg(&feat[c1 * 32 + lane]);
        float4 v2 = __ldg(&feat[c2 * 32 + lane]);
        float4 v3 = __ldg(&feat[c3 * 32 + lane]);
        ax += (v0.x + v1.x) + (v2.x + v3.x);
        ay += (v0.y + v1.y) + (v2.y + v3.y);
        az += (v0.z + v1.z) + (v2.z + v3.z);
        aw += (v0.w + v1.w) + (v2.w + v3.w);
    }
    for (; i < e; i++) {
        int c0 = __ldg(&col[i]);
        float4 v0 = __ldg(&feat[c0 * 32 + lane]);
        ax += v0.x; ay += v0.y; az += v0.z; aw += v0.w;
    }
    float inv = 1.0f / (float)max(e - s, 1);
    out[w * 32 + lane] = make_float4(ax * inv, ay * inv, az * inv, aw * inv);
}

// ---------------- x_mix init: out = r*x + (1-r)*x[perm] ----------------
__global__ void k_mix_init(const float4* __restrict__ x, const int* __restrict__ perm,
                           const float* __restrict__ mixr, float4* __restrict__ out, int n) {
    int idx = blockIdx.x * blockDim.x + threadIdx.x;
    if (idx >= n * 32) return;
    int row = idx >> 5, lane = idx & 31;
    int p = __ldg(&perm[row]);
    float r = __ldg(mixr);
    float q = 1.0f - r;
    float4 a = __ldg(&x[idx]);
    float4 b = __ldg(&x[p * 32 + lane]);
    out[idx] = make_float4(r * a.x + q * b.x, r * a.y + q * b.y,
                           r * a.z + q * b.z, r * a.w + q * b.w);
}

// ---------------- GEMM: out = [relu]( A1@W1 (+ A2@W2) (+ bias) ) ----------------
// M x 128, K=128 per matrix. Block: 128 rows x 128 cols, 256 threads, 8x8/thread.
__global__ __launch_bounds__(256) void k_gemm(
    const float* __restrict__ A1, const float* __restrict__ A2,
    const float* __restrict__ W1, const float* __restrict__ W2,
    const float* __restrict__ bias, float* __restrict__ out,
    int M, int do_relu) {
    __shared__ float Ws[16 * 128];
    __shared__ float As[128 * 17];
    int tid = threadIdx.x;
    int tx = tid & 15, ty = tid >> 4;
    int row0 = blockIdx.x * 128;

    float2 acc[8][4];
#pragma unroll
    for (int r = 0; r < 8; r++)
#pragma unroll
        for (int q = 0; q < 4; q++) acc[r][q] = make_float2(0.f, 0.f);

    int nA = A2 ? 2 : 1;
    for (int p = 0; p < nA; p++) {
        const float* A = p ? A2 : A1;
        const float* W = p ? W2 : W1;
        for (int kc = 0; kc < 8; kc++) {
#pragma unroll
            for (int j = 0; j < 2; j++) {
                int f = tid + j * 256;                 // 512 float4 of W chunk
                int kl = f >> 5, n4 = f & 31;
                float4 wv = __ldg((const float4*)(W + (kc * 16 + kl) * 128 + n4 * 4));
                *(float4*)&Ws[kl * 128 + n4 * 4] = wv;
            }
#pragma unroll
            for (int j = 0; j < 2; j++) {
                int f = tid + j * 256;                 // 512 float4 of A chunk
                int row = f >> 2, kq = f & 3;
                int rg = row0 + row;
                float4 av = (rg < M) ? __ldg((const float4*)(A + rg * 128 + kc * 16 + kq * 4))
                                     : make_float4(0.f, 0.f, 0.f, 0.f);
                float* d = &As[row * 17 + kq * 4];
                d[0] = av.x; d[1] = av.y; d[2] = av.z; d[3] = av.w;
            }
            __syncthreads();
#pragma unroll
            for (int k = 0; k < 16; k++) {
                float4 b0 = *(float4*)&Ws[k * 128 + tx * 8];
                float4 b1 = *(float4*)&Ws[k * 128 + tx * 8 + 4];
                float2 bp[4] = { make_float2(b0.x, b0.y), make_float2(b0.z, b0.w),
                                 make_float2(b1.x, b1.y), make_float2(b1.z, b1.w) };
#pragma unroll
                for (int r = 0; r < 8; r++) {
                    float a = As[(ty * 8 + r) * 17 + k];
                    float2 ad = make_float2(a, a);
                    acc[r][0] = ffma2(ad, bp[0], acc[r][0]);
                    acc[r][1] = ffma2(ad, bp[1], acc[r][1]);
                    acc[r][2] = ffma2(ad, bp[2], acc[r][2]);
                    acc[r][3] = ffma2(ad, bp[3], acc[r][3]);
                }
            }
            __syncthreads();
        }
    }
    float2 bv[4];
#pragma unroll
    for (int q = 0; q < 4; q++)
        bv[q] = bias ? *(const float2*)(bias + tx * 8 + q * 2) : make_float2(0.f, 0.f);
#pragma unroll
    for (int r = 0; r < 8; r++) {
        int rg = row0 + ty * 8 + r;
        if (rg < M) {
#pragma unroll
            for (int q = 0; q < 4; q++) {
                float vx = acc[r][q].x + bv[q].x;
                float vy = acc[r][q].y + bv[q].y;
                if (do_relu) { vx = fmaxf(vx, 0.f); vy = fmaxf(vy, 0.f); }
                *(float2*)(out + rg * 128 + tx * 8 + q * 2) = make_float2(vx, vy);
            }
        }
    }
}

// ---------------- dual GEMM with shared W + mixup epilogue ----------------
// out = r*relu(A1@W + Z + b) + (1-r)*relu(A2@W + Z + b)
__global__ __launch_bounds__(256, 1) void k_gemm_mix(
    const float* __restrict__ A1, const float* __restrict__ A2,
    const float* __restrict__ W, const float* __restrict__ Z,
    const float* __restrict__ bias, const float* __restrict__ mixr,
    float* __restrict__ out, int M) {
    __shared__ float Ws[16 * 128];
    __shared__ float As1[128 * 17];
    __shared__ float As2[128 * 17];
    int tid = threadIdx.x;
    int tx = tid & 15, ty = tid >> 4;
    int row0 = blockIdx.x * 128;

    float2 accA[8][4], accB[8][4];
#pragma unroll
    for (int r = 0; r < 8; r++)
#pragma unroll
        for (int q = 0; q < 4; q++) { accA[r][q] = make_float2(0.f, 0.f); accB[r][q] = make_float2(0.f, 0.f); }

    for (int kc = 0; kc < 8; kc++) {
#pragma unroll
        for (int j = 0; j < 2; j++) {
            int f = tid + j * 256;
            int kl = f >> 5, n4 = f & 31;
            float4 wv = __ldg((const float4*)(W + (kc * 16 + kl) * 128 + n4 * 4));
            *(float4*)&Ws[kl * 128 + n4 * 4] = wv;
        }
#pragma unroll
        for (int j = 0; j < 2; j++) {
            int f = tid + j * 256;
            int row = f >> 2, kq = f & 3;
            int rg = row0 + row;
            float4 a1 = (rg < M) ? __ldg((const float4*)(A1 + rg * 128 + kc * 16 + kq * 4))
                                 : make_float4(0.f, 0.f, 0.f, 0.f);
            float4 a2 = (rg < M) ? __ldg((const float4*)(A2 + rg * 128 + kc * 16 + kq * 4))
                                 : make_float4(0.f, 0.f, 0.f, 0.f);
            float* d1 = &As1[row * 17 + kq * 4];
            float* d2 = &As2[row * 17 + kq * 4];
            d1[0] = a1.x; d1[1] = a1.y; d1[2] = a1.z; d1[3] = a1.w;
            d2[0] = a2.x; d2[1] = a2.y; d2[2] = a2.z; d2[3] = a2.w;
        }
        __syncthreads();
#pragma unroll
        for (int k = 0; k < 16; k++) {
            float4 b0 = *(float4*)&Ws[k * 128 + tx * 8];
            float4 b1 = *(float4*)&Ws[k * 128 + tx * 8 + 4];
            float2 bp[4] = { make_float2(b0.x, b0.y), make_float2(b0.z, b0.w),
                             make_float2(b1.x, b1.y), make_float2(b1.z, b1.w) };
#pragma unroll
            for (int r = 0; r < 8; r++) {
                float a1 = As1[(ty * 8 + r) * 17 + k];
                float a2 = As2[(ty * 8 + r) * 17 + k];
                float2 a1d = make_float2(a1, a1);
                float2 a2d = make_float2(a2, a2);
#pragma unroll
                for (int q = 0; q < 4; q++) {
                    accA[r][q] = ffma2(a1d, bp[q], accA[r][q]);
                    accB[r][q] = ffma2(a2d, bp[q], accB[r][q]);
                }
            }
        }
        __syncthreads();
    }
    float rr = __ldg(mixr);
    float qq = 1.0f - rr;
    float2 bv[4];
#pragma unroll
    for (int q = 0; q < 4; q++) bv[q] = *(const float2*)(bias + tx * 8 + q * 2);
#pragma unroll
    for (int r = 0; r < 8; r++) {
        int rg = row0 + ty * 8 + r;
        if (rg < M) {
#pragma unroll
            for (int q = 0; q < 4; q++) {
                float2 z2 = *(const float2*)(Z + rg * 128 + tx * 8 + q * 2);
                float vax = fmaxf(accA[r][q].x + z2.x + bv[q].x, 0.f);
                float vay = fmaxf(accA[r][q].y + z2.y + bv[q].y, 0.f);
                float vbx = fmaxf(accB[r][q].x + z2.x + bv[q].x, 0.f);
                float vby = fmaxf(accB[r][q].y + z2.y + bv[q].y, 0.f);
                *(float2*)(out + rg * 128 + tx * 8 + q * 2) =
                    make_float2(rr * vax + qq * vbx, rr * vay + qq * vby);
            }
        }
    }
}

// ---------------- logits + log_softmax ----------------
// block: 64 rows, 4 threads/row, 10 classes/thread
__global__ __launch_bounds__(256) void k_logits(
    const float* __restrict__ X, const float* __restrict__ Wo,
    const float* __restrict__ bo, float* __restrict__ out, int n) {
    __shared__ float Ws[128 * 40];
    __shared__ float bs[40];
    int tid = threadIdx.x;
    for (int i = tid; i < 128 * 40; i += 256) Ws[i] = Wo[i];
    if (tid < 40) bs[tid] = bo[tid];
    __syncthreads();

    int row = blockIdx.x * 64 + (tid >> 2);
    int row_c = min(row, n - 1);
    int cg = (tid & 3) * 10;

    float acc[10];
#pragma unroll
    for (int j = 0; j < 10; j++) acc[j] = bs[cg + j];

    const float4* xr = (const float4*)(X + row_c * 128);
#pragma unroll 8
    for (int k4 = 0; k4 < 32; k4++) {
        float4 xv = __ldg(&xr[k4]);
        float xs[4] = { xv.x, xv.y, xv.z, xv.w };
#pragma unroll
        for (int kk = 0; kk < 4; kk++) {
            int k = k4 * 4 + kk;
#pragma unroll
            for (int j = 0; j < 10; j++)
                acc[j] = fmaf(xs[kk], Ws[k * 40 + cg + j], acc[j]);
        }
    }
    float m = acc[0];
#pragma unroll
    for (int j = 1; j < 10; j++) m = fmaxf(m, acc[j]);
    m = fmaxf(m, __shfl_xor_sync(0xffffffffu, m, 1));
    m = fmaxf(m, __shfl_xor_sync(0xffffffffu, m, 2));
    float s = 0.f;
#pragma unroll
    for (int j = 0; j < 10; j++) s += expf(acc[j] - m);
    s += __shfl_xor_sync(0xffffffffu, s, 1);
    s += __shfl_xor_sync(0xffffffffu, s, 2);
    float lse = m + logf(s);
    if (row < n) {
#pragma unroll
        for (int j = 0; j < 10; j++) out[row * 40 + cg + j] = acc[j] - lse;
    }
}

// ---------------- launch ----------------
extern "C" void kernel_launch(void* const* d_in, const int* in_sizes, int n_in,
                              void* d_out, int out_size) {
    const float* x    = (const float*)d_in[0];
    const float* Wl   = (const float*)d_in[1];   // [3,128,128]
    const float* bl   = (const float*)d_in[2];   // [3,128]
    const float* Wr   = (const float*)d_in[3];   // [3,128,128]
    const float* Wo   = (const float*)d_in[4];   // [128,40]
    const float* bo   = (const float*)d_in[5];   // [40]
    const float* mixr = (const float*)d_in[6];   // scalar
    const int*   adj  = (const int*)d_in[7];     // [2,E]
    const int*   adjb = (const int*)d_in[8];     // [2,E]
    const int*   perm = (const int*)d_in[9];     // [N]

    int N = in_sizes[0] / 128;
    int E = in_sizes[7] / 2;

    float *agg0, *agg1, *agga2, *aggb, *h1, *h2, *z, *mix0, *mix1;
    int *cnt, *rpa, *rpb, *cur, *cola, *colb;
    cudaGetSymbolAddress((void**)&agg0, g_agg0);
    cudaGetSymbolAddress((void**)&agg1, g_agg1);
    cudaGetSymbolAddress((void**)&agga2, g_agga2);
    cudaGetSymbolAddress((void**)&aggb, g_aggb);
    cudaGetSymbolAddress((void**)&h1, g_h1);
    cudaGetSymbolAddress((void**)&h2, g_h2);
    cudaGetSymbolAddress((void**)&z, g_z);
    cudaGetSymbolAddress((void**)&mix0, g_mix0);
    cudaGetSymbolAddress((void**)&mix1, g_mix1);
    cudaGetSymbolAddress((void**)&cnt, g_cnt);
    cudaGetSymbolAddress((void**)&rpa, g_rpa);
    cudaGetSymbolAddress((void**)&rpb, g_rpb);
    cudaGetSymbolAddress((void**)&cur, g_cur);
    cudaGetSymbolAddress((void**)&cola, g_cola);
    cudaGetSymbolAddress((void**)&colb, g_colb);

    int eb = (E + 255) / 256;
    int aggBlocks = (N + 7) / 8;           // 8 warps/block, warp/node
    int gemmBlocks = (N + 127) / 128;
    int mixBlocks = (N * 32 + 255) / 256;

    // ---- CSR build: adj ----
    cudaMemsetAsync(cnt, 0, N * sizeof(int));
    k_count<<<eb, 256>>>(adj + E, cnt, E);
    k_scan<<<1, 1024>>>(cnt, rpa, N);
    cudaMemcpyAsync(cur, rpa, N * sizeof(int), cudaMemcpyDeviceToDevice);
    k_fill<<<eb, 256>>>(adj, adj + E, cur, cola, nullptr, E);
    // ---- CSR build: adj_b with perm composed into src ----
    cudaMemsetAsync(cnt, 0, N * sizeof(int));
    k_count<<<eb, 256>>>(adjb + E, cnt, E);
    k_scan<<<1, 1024>>>(cnt, rpb, N);
    cudaMemcpyAsync(cur, rpb, N * sizeof(int), cudaMemcpyDeviceToDevice);
    k_fill<<<eb, 256>>>(adjb, adjb + E, cur, colb, perm, E);

    const float* Wl0 = Wl;            const float* Wl1 = Wl + 16384;  const float* Wl2 = Wl + 32768;
    const float* Wr0 = Wr;            const float* Wr1 = Wr + 16384;  const float* Wr2 = Wr + 32768;
    const float* bl0 = bl;            const float* bl1 = bl + 128;    const float* bl2 = bl + 256;

    // ---- pre-aggregation passes ----
    k_agg<<<aggBlocks, 256>>>((const float4*)x, rpa, cola, (float4*)agg0, N);
    k_gemm<<<gemmBlocks, 256>>>(agg0, x, Wl0, Wr0, bl0, h1, N, 1);
    k_agg<<<aggBlocks, 256>>>((const float4*)h1, rpa, cola, (float4*)agg1, N);
    k_gemm<<<gemmBlocks, 256>>>(agg1, h1, Wl1, Wr1, bl1, h2, N, 1);

    // ---- x_mix init ----
    k_mix_init<<<mixBlocks, 256>>>((const float4*)x, perm, mixr, (float4*)mix0, N);

    // ---- dual-branch layer 0 ----
    k_agg<<<aggBlocks, 256>>>((const float4*)x, rpb, colb, (float4*)aggb, N);
    k_gemm<<<gemmBlocks, 256>>>(mix0, nullptr, Wr0, nullptr, nullptr, z, N, 0);
    k_gemm_mix<<<gemmBlocks, 256>>>(agg0, aggb, Wl0, z, bl0, mixr, mix1, N);

    // ---- dual-branch layer 1 ----
    k_agg<<<aggBlocks, 256>>>((const float4*)h1, rpb, colb, (float4*)aggb, N);
    k_gemm<<<gemmBlocks, 256>>>(mix1, nullptr, Wr1, nullptr, nullptr, z, N, 0);
    k_gemm_mix<<<gemmBlocks, 256>>>(agg1, aggb, Wl1, z, bl1, mixr, mix0, N);

    // ---- dual-branch layer 2 ----
    k_agg<<<aggBlocks, 256>>>((const float4*)h2, rpa, cola, (float4*)agga2, N);
    k_agg<<<aggBlocks, 256>>>((const float4*)h2, rpb, colb, (float4*)aggb, N);
    k_gemm<<<gemmBlocks, 256>>>(mix0, nullptr, Wr2, nullptr, nullptr, z, N, 0);
    k_gemm_mix<<<gemmBlocks, 256>>>(agga2, aggb, Wl2, z, bl2, mixr, mix1, N);

    // ---- logits + log_softmax ----
    k_logits<<<(N + 63) / 64, 256>>>(mix1, Wo, bo, (float*)d_out, N);
}

// round 2
// speedup vs baseline: 1.4474x; 1.4474x over previous
#include <cuda_runtime.h>
#include <cstdint>

#define NN 100000
#define EE 1600000

// ---------------- scratch ----------------
__device__ __align__(16) float g_Y[NN * 128];
__device__ __align__(16) float g_R[NN * 128];
__device__ __align__(16) float g_Z[NN * 128];
__device__ __align__(16) float g_h[NN * 128];
__device__ __align__(16) float g_mixA[NN * 128];
__device__ __align__(16) float g_mixB[NN * 128];

__device__ int g_cnt[NN];
__device__ int g_rpa[NN + 1];
__device__ int g_rpb[NN + 1];
__device__ int g_cur[NN];
__device__ int g_cola[EE];
__device__ int g_colb[EE];

// ---------------- helpers ----------------
__device__ __forceinline__ float2 ffma2(float2 a, float2 b, float2 c) {
    unsigned long long au = *reinterpret_cast<unsigned long long*>(&a);
    unsigned long long bu = *reinterpret_cast<unsigned long long*>(&b);
    unsigned long long cu = *reinterpret_cast<unsigned long long*>(&c);
    unsigned long long du;
    asm("fma.rn.f32x2 %0, %1, %2, %3;" : "=l"(du) : "l"(au), "l"(bu), "l"(cu));
    return *reinterpret_cast<float2*>(&du);
}

// ---------------- CSR build ----------------
__global__ void k_count(const int* __restrict__ dst, int* __restrict__ cnt, int E) {
    int i = blockIdx.x * blockDim.x + threadIdx.x;
    if (i < E) atomicAdd(&cnt[dst[i]], 1);
}

__global__ void k_scan(const int* __restrict__ cnt, int* __restrict__ rowptr, int n) {
    __shared__ int part[1024];
    int tid = threadIdx.x;
    int chunk = (n + 1023) >> 10;
    int s0 = tid * chunk;
    int s1 = min(s0 + chunk, n);
    int s = 0;
    for (int i = s0; i < s1; i++) s += cnt[i];
    part[tid] = s;
    __syncthreads();
    for (int off = 1; off < 1024; off <<= 1) {
        int v = part[tid];
        int u = (tid >= off) ? part[tid - off] : 0;
        __syncthreads();
        part[tid] = v + u;
        __syncthreads();
    }
    int run = (tid == 0) ? 0 : part[tid - 1];
    for (int i = s0; i < s1; i++) { rowptr[i] = run; run += cnt[i]; }
    if (tid == 1023) rowptr[n] = part[1023];
}

__global__ void k_fill(const int* __restrict__ src, const int* __restrict__ dst,
                       int* __restrict__ cursor, int* __restrict__ col,
                       const int* __restrict__ perm, int E) {
    int i = blockIdx.x * blockDim.x + threadIdx.x;
    if (i < E) {
        int d = dst[i];
        int pos = atomicAdd(&cursor[d], 1);
        int s = src[i];
        col[pos] = perm ? perm[s] : s;
    }
}

// ---------------- x_mix init: out = r*x + (1-r)*x[perm] ----------------
__global__ void k_mix_init(const float4* __restrict__ x, const int* __restrict__ perm,
                           const float* __restrict__ mixr, float4* __restrict__ out, int n) {
    int idx = blockIdx.x * blockDim.x + threadIdx.x;
    if (idx >= n * 32) return;
    int row = idx >> 5, lane = idx & 31;
    int p = __ldg(&perm[row]);
    float r = __ldg(mixr);
    float q = 1.0f - r;
    float4 a = __ldg(&x[idx]);
    float4 b = __ldg(&x[p * 32 + lane]);
    out[idx] = make_float4(r * a.x + q * b.x, r * a.y + q * b.y,
                           r * a.z + q * b.z, r * a.w + q * b.w);
}

// ---------------- single GEMM: out = A @ W (no epilogue) ----------------
// 128x128 tile, 256 threads, 8x8/thread. Transposed-A smem for vector LDS.
__global__ __launch_bounds__(256) void k_gemm(
    const float* __restrict__ A, const float* __restrict__ W,
    float* __restrict__ out, int M) {
    __shared__ float Ws[16 * 128];
    __shared__ float As[16 * 132];
    int tid = threadIdx.x;
    int tx = tid & 15, ty = tid >> 4;
    int row0 = blockIdx.x * 128;

    float2 acc[8][4];
#pragma unroll
    for (int r = 0; r < 8; r++)
#pragma unroll
        for (int q = 0; q < 4; q++) acc[r][q] = make_float2(0.f, 0.f);

    for (int kc = 0; kc < 8; kc++) {
#pragma unroll
        for (int j = 0; j < 2; j++) {
            int f = tid + j * 256;
            int kl = f >> 5, n4 = f & 31;
            float4 wv = __ldg((const float4*)(W + (kc * 16 + kl) * 128 + n4 * 4));
            *(float4*)&Ws[kl * 128 + n4 * 4] = wv;
        }
#pragma unroll
        for (int j = 0; j < 2; j++) {
            int f = tid + j * 256;
            int row = f >> 2, kq = f & 3;
            int rg = row0 + row;
            float4 av = (rg < M) ? __ldg((const float4*)(A + rg * 128 + kc * 16 + kq * 4))
                                 : make_float4(0.f, 0.f, 0.f, 0.f);
            As[(kq * 4 + 0) * 132 + row] = av.x;
            As[(kq * 4 + 1) * 132 + row] = av.y;
            As[(kq * 4 + 2) * 132 + row] = av.z;
            As[(kq * 4 + 3) * 132 + row] = av.w;
        }
        __syncthreads();
#pragma unroll
        for (int k = 0; k < 16; k++) {
            float4 a0 = *(float4*)&As[k * 132 + ty * 8];
            float4 a1 = *(float4*)&As[k * 132 + ty * 8 + 4];
            float av[8] = { a0.x, a0.y, a0.z, a0.w, a1.x, a1.y, a1.z, a1.w };
            float4 b0 = *(float4*)&Ws[k * 128 + tx * 8];
            float4 b1 = *(float4*)&Ws[k * 128 + tx * 8 + 4];
            float2 bp[4] = { make_float2(b0.x, b0.y), make_float2(b0.z, b0.w),
                             make_float2(b1.x, b1.y), make_float2(b1.z, b1.w) };
#pragma unroll
            for (int r = 0; r < 8; r++) {
                float2 ad = make_float2(av[r], av[r]);
                acc[r][0] = ffma2(ad, bp[0], acc[r][0]);
                acc[r][1] = ffma2(ad, bp[1], acc[r][1]);
                acc[r][2] = ffma2(ad, bp[2], acc[r][2]);
                acc[r][3] = ffma2(ad, bp[3], acc[r][3]);
            }
        }
        __syncthreads();
    }
#pragma unroll
    for (int r = 0; r < 8; r++) {
        int rg = row0 + ty * 8 + r;
        if (rg < M) {
#pragma unroll
            for (int q = 0; q < 4; q++)
                *(float2*)(out + rg * 128 + tx * 8 + q * 2) = acc[r][q];
        }
    }
}

// ---------------- fused dual aggregation + mixup epilogue ----------------
// aggA = mean gather of Y over CSR-A; aggB = mean gather of Y over CSR-B.
// mixout = r*relu(aggA+Z+b) + (1-r)*relu(aggB+Z+b)
// if hout: hout = relu(aggA + R + b)
__device__ __forceinline__ float4 gather_mean(const float4* __restrict__ Y,
                                              const int* __restrict__ rp,
                                              const int* __restrict__ col,
                                              int w, int lane) {
    int s = __ldg(&rp[w]), e = __ldg(&rp[w + 1]);
    float ax = 0.f, ay = 0.f, az = 0.f, aw = 0.f;
    int i = s;
    for (; i + 3 < e; i += 4) {
        int c0 = __ldg(&col[i + 0]);
        int c1 = __ldg(&col[i + 1]);
        int c2 = __ldg(&col[i + 2]);
        int c3 = __ldg(&col[i + 3]);
        float4 v0 = __ldg(&Y[c0 * 32 + lane]);
        float4 v1 = __ldg(&Y[c1 * 32 + lane]);
        float4 v2 = __ldg(&Y[c2 * 32 + lane]);
        float4 v3 = __ldg(&Y[c3 * 32 + lane]);
        ax += (v0.x + v1.x) + (v2.x + v3.x);
        ay += (v0.y + v1.y) + (v2.y + v3.y);
        az += (v0.z + v1.z) + (v2.z + v3.z);
        aw += (v0.w + v1.w) + (v2.w + v3.w);
    }
    for (; i < e; i++) {
        int c0 = __ldg(&col[i]);
        float4 v0 = __ldg(&Y[c0 * 32 + lane]);
        ax += v0.x; ay += v0.y; az += v0.z; aw += v0.w;
    }
    float inv = 1.0f / (float)max(e - s, 1);
    return make_float4(ax * inv, ay * inv, az * inv, aw * inv);
}

__global__ void k_aggmix(const float4* __restrict__ Y,
                         const int* __restrict__ rpa, const int* __restrict__ cola,
                         const int* __restrict__ rpb, const int* __restrict__ colb,
                         const float4* __restrict__ Z, const float4* __restrict__ R,
                         const float4* __restrict__ bias, const float* __restrict__ mixr,
                         float4* __restrict__ mixout, float4* __restrict__ hout, int n) {
    int w = (blockIdx.x * blockDim.x + threadIdx.x) >> 5;
    int lane = threadIdx.x & 31;
    if (w >= n) return;
    float4 aA = gather_mean(Y, rpa, cola, w, lane);
    float4 aB = gather_mean(Y, rpb, colb, w, lane);
    float4 z = __ldg(&Z[w * 32 + lane]);
    float4 b = __ldg(&bias[lane]);
    float r = __ldg(mixr);
    float q = 1.0f - r;
    float4 sA = make_float4(fmaxf(aA.x + z.x + b.x, 0.f), fmaxf(aA.y + z.y + b.y, 0.f),
                            fmaxf(aA.z + z.z + b.z, 0.f), fmaxf(aA.w + z.w + b.w, 0.f));
    float4 sB = make_float4(fmaxf(aB.x + z.x + b.x, 0.f), fmaxf(aB.y + z.y + b.y, 0.f),
                            fmaxf(aB.z + z.z + b.z, 0.f), fmaxf(aB.w + z.w + b.w, 0.f));
    mixout[w * 32 + lane] = make_float4(r * sA.x + q * sB.x, r * sA.y + q * sB.y,
                                        r * sA.z + q * sB.z, r * sA.w + q * sB.w);
    if (hout) {
        float4 rv = __ldg(&R[w * 32 + lane]);
        hout[w * 32 + lane] = make_float4(
            fmaxf(aA.x + rv.x + b.x, 0.f), fmaxf(aA.y + rv.y + b.y, 0.f),
            fmaxf(aA.z + rv.z + b.z, 0.f), fmaxf(aA.w + rv.w + b.w, 0.f));
    }
}

// ---------------- logits + log_softmax ----------------
__global__ __launch_bounds__(256) void k_logits(
    const float* __restrict__ X, const float* __restrict__ Wo,
    const float* __restrict__ bo, float* __restrict__ out, int n) {
    __shared__ float Ws[128 * 40];
    __shared__ float bs[40];
    int tid = threadIdx.x;
    for (int i = tid; i < 128 * 40; i += 256) Ws[i] = Wo[i];
    if (tid < 40) bs[tid] = bo[tid];
    __syncthreads();

    int row = blockIdx.x * 64 + (tid >> 2);
    int row_c = min(row, n - 1);
    int cg = (tid & 3) * 10;

    float acc[10];
#pragma unroll
    for (int j = 0; j < 10; j++) acc[j] = bs[cg + j];

    const float4* xr = (const float4*)(X + row_c * 128);
#pragma unroll 8
    for (int k4 = 0; k4 < 32; k4++) {
        float4 xv = __ldg(&xr[k4]);
        float xs[4] = { xv.x, xv.y, xv.z, xv.w };
#pragma unroll
        for (int kk = 0; kk < 4; kk++) {
            int k = k4 * 4 + kk;
#pragma unroll
            for (int j = 0; j < 10; j++)
                acc[j] = fmaf(xs[kk], Ws[k * 40 + cg + j], acc[j]);
        }
    }
    float m = acc[0];
#pragma unroll
    for (int j = 1; j < 10; j++) m = fmaxf(m, acc[j]);
    m = fmaxf(m, __shfl_xor_sync(0xffffffffu, m, 1));
    m = fmaxf(m, __shfl_xor_sync(0xffffffffu, m, 2));
    float s = 0.f;
#pragma unroll
    for (int j = 0; j < 10; j++) s += expf(acc[j] - m);
    s += __shfl_xor_sync(0xffffffffu, s, 1);
    s += __shfl_xor_sync(0xffffffffu, s, 2);
    float lse = m + logf(s);
    if (row < n) {
#pragma unroll
        for (int j = 0; j < 10; j++) out[row * 40 + cg + j] = acc[j] - lse;
    }
}

// ---------------- launch ----------------
extern "C" void kernel_launch(void* const* d_in, const int* in_sizes, int n_in,
                              void* d_out, int out_size) {
    const float* x    = (const float*)d_in[0];
    const float* Wl   = (const float*)d_in[1];   // [3,128,128]
    const float* bl   = (const float*)d_in[2];   // [3,128]
    const float* Wr   = (const float*)d_in[3];   // [3,128,128]
    const float* Wo   = (const float*)d_in[4];   // [128,40]
    const float* bo   = (const float*)d_in[5];   // [40]
    const float* mixr = (const float*)d_in[6];   // scalar
    const int*   adj  = (const int*)d_in[7];     // [2,E]
    const int*   adjb = (const int*)d_in[8];     // [2,E]
    const int*   perm = (const int*)d_in[9];     // [N]

    int N = in_sizes[0] / 128;
    int E = in_sizes[7] / 2;

    float *Y, *R, *Z, *h, *mixA, *mixB;
    int *cnt, *rpa, *rpb, *cur, *cola, *colb;
    cudaGetSymbolAddress((void**)&Y, g_Y);
    cudaGetSymbolAddress((void**)&R, g_R);
    cudaGetSymbolAddress((void**)&Z, g_Z);
    cudaGetSymbolAddress((void**)&h, g_h);
    cudaGetSymbolAddress((void**)&mixA, g_mixA);
    cudaGetSymbolAddress((void**)&mixB, g_mixB);
    cudaGetSymbolAddress((void**)&cnt, g_cnt);
    cudaGetSymbolAddress((void**)&rpa, g_rpa);
    cudaGetSymbolAddress((void**)&rpb, g_rpb);
    cudaGetSymbolAddress((void**)&cur, g_cur);
    cudaGetSymbolAddress((void**)&cola, g_cola);
    cudaGetSymbolAddress((void**)&colb, g_colb);

    int eb = (E + 255) / 256;
    int aggBlocks = (N + 7) / 8;
    int gemmBlocks = (N + 127) / 128;
    int mixBlocks = (N * 32 + 255) / 256;

    const float* Wl0 = Wl;  const float* Wl1 = Wl + 16384;  const float* Wl2 = Wl + 32768;
    const float* Wr0 = Wr;  const float* Wr1 = Wr + 16384;  const float* Wr2 = Wr + 32768;
    const float4* bl0 = (const float4*)bl;
    const float4* bl1 = (const float4*)(bl + 128);
    const float4* bl2 = (const float4*)(bl + 256);

    // ---- CSR build: adj ----
    cudaMemsetAsync(cnt, 0, N * sizeof(int));
    k_count<<<eb, 256>>>(adj + E, cnt, E);
    k_scan<<<1, 1024>>>(cnt, rpa, N);
    cudaMemcpyAsync(cur, rpa, N * sizeof(int), cudaMemcpyDeviceToDevice);
    k_fill<<<eb, 256>>>(adj, adj + E, cur, cola, nullptr, E);
    // ---- CSR build: adj_b with perm composed into src ----
    cudaMemsetAsync(cnt, 0, N * sizeof(int));
    k_count<<<eb, 256>>>(adjb + E, cnt, E);
    k_scan<<<1, 1024>>>(cnt, rpb, N);
    cudaMemcpyAsync(cur, rpb, N * sizeof(int), cudaMemcpyDeviceToDevice);
    k_fill<<<eb, 256>>>(adjb, adjb + E, cur, colb, perm, E);

    // ---- x_mix init ----
    k_mix_init<<<mixBlocks, 256>>>((const float4*)x, perm, mixr, (float4*)mixA, N);

    // ---- layer 0 ----
    k_gemm<<<gemmBlocks, 256>>>(x, Wl0, Y, N);        // Y0 = x@Wl0
    k_gemm<<<gemmBlocks, 256>>>(x, Wr0, R, N);        // R0 = x@Wr0
    k_gemm<<<gemmBlocks, 256>>>(mixA, Wr0, Z, N);     // Z0 = mix0@Wr0
    k_aggmix<<<aggBlocks, 256>>>((const float4*)Y, rpa, cola, rpb, colb,
                                 (const float4*)Z, (const float4*)R, bl0, mixr,
                                 (float4*)mixB, (float4*)h, N);   // -> mix1, h1

    // ---- layer 1 ----
    k_gemm<<<gemmBlocks, 256>>>(h, Wl1, Y, N);        // Y1 = h1@Wl1
    k_gemm<<<gemmBlocks, 256>>>(h, Wr1, R, N);        // R1 = h1@Wr1
    k_gemm<<<gemmBlocks, 256>>>(mixB, Wr1, Z, N);     // Z1 = mix1@Wr1
    k_aggmix<<<aggBlocks, 256>>>((const float4*)Y, rpa, cola, rpb, colb,
                                 (const float4*)Z, (const float4*)R, bl1, mixr,
                                 (float4*)mixA, (float4*)h, N);   // -> mix2, h2

    // ---- layer 2 ----
    k_gemm<<<gemmBlocks, 256>>>(h, Wl2, Y, N);        // Y2 = h2@Wl2
    k_gemm<<<gemmBlocks, 256>>>(mixA, Wr2, Z, N);     // Z2 = mix2@Wr2
    k_aggmix<<<aggBlocks, 256>>>((const float4*)Y, rpa, cola, rpb, colb,
                                 (const float4*)Z, nullptr, bl2, mixr,
                                 (float4*)mixB, nullptr, N);      // -> mix3

    // ---- logits + log_softmax ----
    k_logits<<<(N + 63) / 64, 256>>>(mixB, Wo, bo, (float*)d_out, N);
}

// round 3
// speedup vs baseline: 2.0287x; 1.4016x over previous
#include <cuda_runtime.h>
#include <cuda_bf16.h>
#include <cstdint>

#define NN 100000
#define EE 1600000

// ---------------- scratch ----------------
__device__ __align__(16) float g_Y[NN * 128];
__device__ __align__(16) float g_R[NN * 128];
__device__ __align__(16) float g_Z[NN * 128];
__device__ __align__(16) float g_mixF[NN * 128];
__device__ __align__(16) __nv_bfloat16 g_xhi[NN * 128];
__device__ __align__(16) __nv_bfloat16 g_xlo[NN * 128];
__device__ __align__(16) __nv_bfloat16 g_hhi[NN * 128];
__device__ __align__(16) __nv_bfloat16 g_hlo[NN * 128];
__device__ __align__(16) __nv_bfloat16 g_mhi[NN * 128];
__device__ __align__(16) __nv_bfloat16 g_mlo[NN * 128];
__device__ __align__(16) __nv_bfloat16 g_Wthi[6 * 128 * 128];
__device__ __align__(16) __nv_bfloat16 g_Wtlo[6 * 128 * 128];

__device__ int g_cnt[NN];
__device__ int g_rpa[NN + 1];
__device__ int g_rpb[NN + 1];
__device__ int g_cur[NN];
__device__ int g_cola[EE];
__device__ int g_colb[EE];

// ---------------- helpers ----------------
__device__ __forceinline__ uint32_t pack_bf2(__nv_bfloat16 a, __nv_bfloat16 b) {
    __nv_bfloat162 t = __halves2bfloat162(a, b);
    return *reinterpret_cast<uint32_t*>(&t);
}

__device__ __forceinline__ void split_store4(float4 v, __nv_bfloat16* hi,
                                             __nv_bfloat16* lo, int off) {
    __nv_bfloat16 hx = __float2bfloat16(v.x);
    __nv_bfloat16 hy = __float2bfloat16(v.y);
    __nv_bfloat16 hz = __float2bfloat16(v.z);
    __nv_bfloat16 hw = __float2bfloat16(v.w);
    uint2 hv, lv;
    hv.x = pack_bf2(hx, hy);
    hv.y = pack_bf2(hz, hw);
    lv.x = pack_bf2(__float2bfloat16(v.x - __bfloat162float(hx)),
                    __float2bfloat16(v.y - __bfloat162float(hy)));
    lv.y = pack_bf2(__float2bfloat16(v.z - __bfloat162float(hz)),
                    __float2bfloat16(v.w - __bfloat162float(hw)));
    *reinterpret_cast<uint2*>(hi + off) = hv;
    *reinterpret_cast<uint2*>(lo + off) = lv;
}

__device__ __forceinline__ void mma_bf16(float* c, const uint32_t* a,
                                         uint32_t b0, uint32_t b1) {
    asm volatile(
        "mma.sync.aligned.m16n8k16.row.col.f32.bf16.bf16.f32 "
        "{%0,%1,%2,%3}, {%4,%5,%6,%7}, {%8,%9}, {%0,%1,%2,%3};"
        : "+f"(c[0]), "+f"(c[1]), "+f"(c[2]), "+f"(c[3])
        : "r"(a[0]), "r"(a[1]), "r"(a[2]), "r"(a[3]), "r"(b0), "r"(b1));
}

// ---------------- CSR build ----------------
__global__ void k_count(const int* __restrict__ dst, int* __restrict__ cnt, int E) {
    int i = blockIdx.x * blockDim.x + threadIdx.x;
    if (i < E) atomicAdd(&cnt[dst[i]], 1);
}

__global__ void k_scan(const int* __restrict__ cnt, int* __restrict__ rowptr, int n) {
    __shared__ int part[1024];
    int tid = threadIdx.x;
    int chunk = (n + 1023) >> 10;
    int s0 = tid * chunk;
    int s1 = min(s0 + chunk, n);
    int s = 0;
    for (int i = s0; i < s1; i++) s += cnt[i];
    part[tid] = s;
    __syncthreads();
    for (int off = 1; off < 1024; off <<= 1) {
        int v = part[tid];
        int u = (tid >= off) ? part[tid - off] : 0;
        __syncthreads();
        part[tid] = v + u;
        __syncthreads();
    }
    int run = (tid == 0) ? 0 : part[tid - 1];
    for (int i = s0; i < s1; i++) { rowptr[i] = run; run += cnt[i]; }
    if (tid == 1023) rowptr[n] = part[1023];
}

__global__ void k_fill(const int* __restrict__ src, const int* __restrict__ dst,
                       int* __restrict__ cursor, int* __restrict__ col,
                       const int* __restrict__ perm, int E) {
    int i = blockIdx.x * blockDim.x + threadIdx.x;
    if (i < E) {
        int d = dst[i];
        int pos = atomicAdd(&cursor[d], 1);
        int s = src[i];
        col[pos] = perm ? perm[s] : s;
    }
}

// ---------------- weight prep: transpose + bf16 split ----------------
// Wt[n][k] = W[k][n]; matrices 0..2 = Wl, 3..5 = Wr
__global__ void k_wprep(const float* __restrict__ Wl, const float* __restrict__ Wr,
                        __nv_bfloat16* __restrict__ Wthi, __nv_bfloat16* __restrict__ Wtlo) {
    int i = blockIdx.x * blockDim.x + threadIdx.x;
    if (i >= 6 * 16384) return;
    int m = i >> 14;
    int r = (i >> 7) & 127;   // k
    int c = i & 127;          // n
    const float* W = (m < 3) ? (Wl + m * 16384) : (Wr + (m - 3) * 16384);
    float v = W[r * 128 + c];
    __nv_bfloat16 h = __float2bfloat16(v);
    Wthi[m * 16384 + c * 128 + r] = h;
    Wtlo[m * 16384 + c * 128 + r] = __float2bfloat16(v - __bfloat162float(h));
}

// ---------------- x split ----------------
__global__ void k_split(const float4* __restrict__ x, __nv_bfloat16* __restrict__ hi,
                        __nv_bfloat16* __restrict__ lo, int n4) {
    int i = blockIdx.x * blockDim.x + threadIdx.x;
    if (i >= n4) return;
    split_store4(__ldg(&x[i]), hi, lo, i * 4);
}

// ---------------- x_mix init -> bf16 hi/lo ----------------
__global__ void k_mix_init(const float4* __restrict__ x, const int* __restrict__ perm,
                           const float* __restrict__ mixr,
                           __nv_bfloat16* __restrict__ mhi, __nv_bfloat16* __restrict__ mlo,
                           int n) {
    int idx = blockIdx.x * blockDim.x + threadIdx.x;
    if (idx >= n * 32) return;
    int row = idx >> 5, lane = idx & 31;
    int p = __ldg(&perm[row]);
    float r = __ldg(mixr);
    float q = 1.0f - r;
    float4 a = __ldg(&x[idx]);
    float4 b = __ldg(&x[p * 32 + lane]);
    float4 v = make_float4(r * a.x + q * b.x, r * a.y + q * b.y,
                           r * a.z + q * b.z, r * a.w + q * b.w);
    split_store4(v, mhi, mlo, idx * 4);
}

// ---------------- tensor-core GEMM: out = (Ahi+Alo) @ (Whi+Wlo), bf16x3 ----------------
// A: [M][128] bf16 hi/lo (row-major); W transposed [n][k] bf16 hi/lo.
// Block: 128x128 tile, 256 threads (8 warps: 4 m x 2 n). K chunked 2x64.
#define PITCHW 36   // words per row in smem: 32 data + 4 pad
__global__ __launch_bounds__(256) void k_gemm_tc(
    const __nv_bfloat16* __restrict__ Ahi, const __nv_bfloat16* __restrict__ Alo,
    const __nv_bfloat16* __restrict__ Wthi, const __nv_bfloat16* __restrict__ Wtlo,
    float* __restrict__ out, int M) {
    extern __shared__ uint32_t sm[];
    uint32_t* sWh = sm;                 // 128 * 36
    uint32_t* sWl = sm + 128 * PITCHW;
    uint32_t* sAh = sm + 2 * 128 * PITCHW;
    uint32_t* sAl = sm + 3 * 128 * PITCHW;
    int tid = threadIdx.x;
    int w = tid >> 5, lane = tid & 31;
    int g = lane >> 2, tg = lane & 3;
    int m0 = (w & 3) * 32;
    int n0 = (w >> 2) * 64;
    int row0 = blockIdx.x * 128;

    float acc[2][8][4];
#pragma unroll
    for (int mi = 0; mi < 2; mi++)
#pragma unroll
        for (int j = 0; j < 8; j++)
#pragma unroll
            for (int q = 0; q < 4; q++) acc[mi][j][q] = 0.f;

    for (int kc = 0; kc < 2; kc++) {
        int k0 = kc * 64;
        if (kc) __syncthreads();
#pragma unroll
        for (int j = 0; j < 4; j++) {
            int f = tid + j * 256;        // 0..1023
            int r = f >> 3, q = f & 7;
            size_t goff = (size_t)r * 256 + k0 * 2 + q * 16;  // bytes within [128][128]bf16
            uint4 wh = *(const uint4*)((const char*)Wthi + goff);
            uint4 wl = *(const uint4*)((const char*)Wtlo + goff);
            *(uint4*)&sWh[r * PITCHW + q * 4] = wh;
            *(uint4*)&sWl[r * PITCHW + q * 4] = wl;
            int rg = row0 + r;
            uint4 ah = make_uint4(0, 0, 0, 0), al = make_uint4(0, 0, 0, 0);
            if (rg < M) {
                size_t aoff = (size_t)rg * 256 + k0 * 2 + q * 16;
                ah = *(const uint4*)((const char*)Ahi + aoff);
                al = *(const uint4*)((const char*)Alo + aoff);
            }
            *(uint4*)&sAh[r * PITCHW + q * 4] = ah;
            *(uint4*)&sAl[r * PITCHW + q * 4] = al;
        }
        __syncthreads();
#pragma unroll
        for (int kb = 0; kb < 4; kb++) {
            int pa = kb * 8 + tg;
            uint32_t ah[2][4], al_[2][4];
#pragma unroll
            for (int mi = 0; mi < 2; mi++) {
                int rb = (m0 + mi * 16 + g) * PITCHW;
                ah[mi][0] = sAh[rb + pa];
                ah[mi][1] = sAh[rb + 8 * PITCHW + pa];
                ah[mi][2] = sAh[rb + pa + 4];
                ah[mi][3] = sAh[rb + 8 * PITCHW + pa + 4];
                al_[mi][0] = sAl[rb + pa];
                al_[mi][1] = sAl[rb + 8 * PITCHW + pa];
                al_[mi][2] = sAl[rb + pa + 4];
                al_[mi][3] = sAl[rb + 8 * PITCHW + pa + 4];
            }
#pragma unroll
            for (int j = 0; j < 8; j++) {
                int nb = (n0 + j * 8 + g) * PITCHW;
                uint32_t bh0 = sWh[nb + pa], bh1 = sWh[nb + pa + 4];
                uint32_t bl0 = sWl[nb + pa], bl1 = sWl[nb + pa + 4];
#pragma unroll
                for (int mi = 0; mi < 2; mi++) {
                    mma_bf16(acc[mi][j], ah[mi], bh0, bh1);
                    mma_bf16(acc[mi][j], ah[mi], bl0, bl1);
                    mma_bf16(acc[mi][j], al_[mi], bh0, bh1);
                }
            }
        }
    }
    // store: c0,c1 -> row g; c2,c3 -> row g+8; cols n0+j*8+2tg
#pragma unroll
    for (int mi = 0; mi < 2; mi++) {
        int r1 = row0 + m0 + mi * 16 + g;
        int r2 = r1 + 8;
#pragma unroll
        for (int j = 0; j < 8; j++) {
            int cidx = n0 + j * 8 + 2 * tg;
            if (r1 < M)
                *(float2*)(out + (size_t)r1 * 128 + cidx) = make_float2(acc[mi][j][0], acc[mi][j][1]);
            if (r2 < M)
                *(float2*)(out + (size_t)r2 * 128 + cidx) = make_float2(acc[mi][j][2], acc[mi][j][3]);
        }
    }
}

// ---------------- fused dual aggregation + mixup epilogue ----------------
__device__ __forceinline__ float4 gather_mean(const float4* __restrict__ Y,
                                              const int* __restrict__ rp,
                                              const int* __restrict__ col,
                                              int w, int lane) {
    int s = __ldg(&rp[w]), e = __ldg(&rp[w + 1]);
    float ax = 0.f, ay = 0.f, az = 0.f, aw = 0.f;
    int i = s;
    for (; i + 3 < e; i += 4) {
        int c0 = __ldg(&col[i + 0]);
        int c1 = __ldg(&col[i + 1]);
        int c2 = __ldg(&col[i + 2]);
        int c3 = __ldg(&col[i + 3]);
        float4 v0 = __ldg(&Y[c0 * 32 + lane]);
        float4 v1 = __ldg(&Y[c1 * 32 + lane]);
        float4 v2 = __ldg(&Y[c2 * 32 + lane]);
        float4 v3 = __ldg(&Y[c3 * 32 + lane]);
        ax += (v0.x + v1.x) + (v2.x + v3.x);
        ay += (v0.y + v1.y) + (v2.y + v3.y);
        az += (v0.z + v1.z) + (v2.z + v3.z);
        aw += (v0.w + v1.w) + (v2.w + v3.w);
    }
    for (; i < e; i++) {
        int c0 = __ldg(&col[i]);
        float4 v0 = __ldg(&Y[c0 * 32 + lane]);
        ax += v0.x; ay += v0.y; az += v0.z; aw += v0.w;
    }
    float inv = 1.0f / (float)max(e - s, 1);
    return make_float4(ax * inv, ay * inv, az * inv, aw * inv);
}

__global__ void k_aggmix(const float4* __restrict__ Y,
                         const int* __restrict__ rpa, const int* __restrict__ cola,
                         const int* __restrict__ rpb, const int* __restrict__ colb,
                         const float4* __restrict__ Z, const float4* __restrict__ R,
                         const float4* __restrict__ bias, const float* __restrict__ mixr,
                         __nv_bfloat16* __restrict__ mhi, __nv_bfloat16* __restrict__ mlo,
                         float4* __restrict__ mixF,
                         __nv_bfloat16* __restrict__ hhi, __nv_bfloat16* __restrict__ hlo,
                         int n) {
    int w = (blockIdx.x * blockDim.x + threadIdx.x) >> 5;
    int lane = threadIdx.x & 31;
    if (w >= n) return;
    float4 aA = gather_mean(Y, rpa, cola, w, lane);
    float4 aB = gather_mean(Y, rpb, colb, w, lane);
    float4 z = __ldg(&Z[w * 32 + lane]);
    float4 b = __ldg(&bias[lane]);
    float r = __ldg(mixr);
    float q = 1.0f - r;
    float4 sA = make_float4(fmaxf(aA.x + z.x + b.x, 0.f), fmaxf(aA.y + z.y + b.y, 0.f),
                            fmaxf(aA.z + z.z + b.z, 0.f), fmaxf(aA.w + z.w + b.w, 0.f));
    float4 sB = make_float4(fmaxf(aB.x + z.x + b.x, 0.f), fmaxf(aB.y + z.y + b.y, 0.f),
                            fmaxf(aB.z + z.z + b.z, 0.f), fmaxf(aB.w + z.w + b.w, 0.f));
    float4 mix = make_float4(r * sA.x + q * sB.x, r * sA.y + q * sB.y,
                             r * sA.z + q * sB.z, r * sA.w + q * sB.w);
    if (mixF) mixF[w * 32 + lane] = mix;
    else split_store4(mix, mhi, mlo, (w * 32 + lane) * 4);
    if (hhi) {
        float4 rv = __ldg(&R[w * 32 + lane]);
        float4 h = make_float4(
            fmaxf(aA.x + rv.x + b.x, 0.f), fmaxf(aA.y + rv.y + b.y, 0.f),
            fmaxf(aA.z + rv.z + b.z, 0.f), fmaxf(aA.w + rv.w + b.w, 0.f));
        split_store4(h, hhi, hlo, (w * 32 + lane) * 4);
    }
}

// ---------------- logits + log_softmax ----------------
__global__ __launch_bounds__(256) void k_logits(
    const float* __restrict__ X, const float* __restrict__ Wo,
    const float* __restrict__ bo, float* __restrict__ out, int n) {
    __shared__ float Ws[128 * 40];
    __shared__ float bs[40];
    int tid = threadIdx.x;
    for (int i = tid; i < 128 * 40; i += 256) Ws[i] = Wo[i];
    if (tid < 40) bs[tid] = bo[tid];
    __syncthreads();

    int row = blockIdx.x * 64 + (tid >> 2);
    int row_c = min(row, n - 1);
    int cg = (tid & 3) * 10;

    float acc[10];
#pragma unroll
    for (int j = 0; j < 10; j++) acc[j] = bs[cg + j];

    const float4* xr = (const float4*)(X + (size_t)row_c * 128);
#pragma unroll 8
    for (int k4 = 0; k4 < 32; k4++) {
        float4 xv = __ldg(&xr[k4]);
        float xs[4] = { xv.x, xv.y, xv.z, xv.w };
#pragma unroll
        for (int kk = 0; kk < 4; kk++) {
            int k = k4 * 4 + kk;
#pragma unroll
            for (int j = 0; j < 10; j++)
                acc[j] = fmaf(xs[kk], Ws[k * 40 + cg + j], acc[j]);
        }
    }
    float m = acc[0];
#pragma unroll
    for (int j = 1; j < 10; j++) m = fmaxf(m, acc[j]);
    m = fmaxf(m, __shfl_xor_sync(0xffffffffu, m, 1));
    m = fmaxf(m, __shfl_xor_sync(0xffffffffu, m, 2));
    float s = 0.f;
#pragma unroll
    for (int j = 0; j < 10; j++) s += expf(acc[j] - m);
    s += __shfl_xor_sync(0xffffffffu, s, 1);
    s += __shfl_xor_sync(0xffffffffu, s, 2);
    float lse = m + logf(s);
    if (row < n) {
#pragma unroll
        for (int j = 0; j < 10; j++) out[row * 40 + cg + j] = acc[j] - lse;
    }
}

// ---------------- launch ----------------
extern "C" void kernel_launch(void* const* d_in, const int* in_sizes, int n_in,
                              void* d_out, int out_size) {
    const float* x    = (const float*)d_in[0];
    const float* Wl   = (const float*)d_in[1];
    const float* bl   = (const float*)d_in[2];
    const float* Wr   = (const float*)d_in[3];
    const float* Wo   = (const float*)d_in[4];
    const float* bo   = (const float*)d_in[5];
    const float* mixr = (const float*)d_in[6];
    const int*   adj  = (const int*)d_in[7];
    const int*   adjb = (const int*)d_in[8];
    const int*   perm = (const int*)d_in[9];

    int N = in_sizes[0] / 128;
    int E = in_sizes[7] / 2;

    float *Y, *R, *Z, *mixF;
    __nv_bfloat16 *xhi, *xlo, *hhi, *hlo, *mhi, *mlo, *Wthi, *Wtlo;
    int *cnt, *rpa, *rpb, *cur, *cola, *colb;
    cudaGetSymbolAddress((void**)&Y, g_Y);
    cudaGetSymbolAddress((void**)&R, g_R);
    cudaGetSymbolAddress((void**)&Z, g_Z);
    cudaGetSymbolAddress((void**)&mixF, g_mixF);
    cudaGetSymbolAddress((void**)&xhi, g_xhi);
    cudaGetSymbolAddress((void**)&xlo, g_xlo);
    cudaGetSymbolAddress((void**)&hhi, g_hhi);
    cudaGetSymbolAddress((void**)&hlo, g_hlo);
    cudaGetSymbolAddress((void**)&mhi, g_mhi);
    cudaGetSymbolAddress((void**)&mlo, g_mlo);
    cudaGetSymbolAddress((void**)&Wthi, g_Wthi);
    cudaGetSymbolAddress((void**)&Wtlo, g_Wtlo);
    cudaGetSymbolAddress((void**)&cnt, g_cnt);
    cudaGetSymbolAddress((void**)&rpa, g_rpa);
    cudaGetSymbolAddress((void**)&rpb, g_rpb);
    cudaGetSymbolAddress((void**)&cur, g_cur);
    cudaGetSymbolAddress((void**)&cola, g_cola);
    cudaGetSymbolAddress((void**)&colb, g_colb);

    static int smem_set = 0;
    const int GEMM_SMEM = 4 * 128 * PITCHW * 4;  // 73728 B
    if (!smem_set) {
        cudaFuncSetAttribute(k_gemm_tc, cudaFuncAttributeMaxDynamicSharedMemorySize, GEMM_SMEM);
        smem_set = 1;
    }

    int eb = (E + 255) / 256;
    int aggBlocks = (N + 7) / 8;
    int gemmBlocks = (N + 127) / 128;
    int mixBlocks = (N * 32 + 255) / 256;

    const float4* bl0 = (const float4*)bl;
    const float4* bl1 = (const float4*)(bl + 128);
    const float4* bl2 = (const float4*)(bl + 256);
    __nv_bfloat16* Wl0h = Wthi + 0 * 16384; __nv_bfloat16* Wl0l = Wtlo + 0 * 16384;
    __nv_bfloat16* Wl1h = Wthi + 1 * 16384; __nv_bfloat16* Wl1l = Wtlo + 1 * 16384;
    __nv_bfloat16* Wl2h = Wthi + 2 * 16384; __nv_bfloat16* Wl2l = Wtlo + 2 * 16384;
    __nv_bfloat16* Wr0h = Wthi + 3 * 16384; __nv_bfloat16* Wr0l = Wtlo + 3 * 16384;
    __nv_bfloat16* Wr1h = Wthi + 4 * 16384; __nv_bfloat16* Wr1l = Wtlo + 4 * 16384;
    __nv_bfloat16* Wr2h = Wthi + 5 * 16384; __nv_bfloat16* Wr2l = Wtlo + 5 * 16384;

    // ---- CSR build ----
    cudaMemsetAsync(cnt, 0, N * sizeof(int));
    k_count<<<eb, 256>>>(adj + E, cnt, E);
    k_scan<<<1, 1024>>>(cnt, rpa, N);
    cudaMemcpyAsync(cur, rpa, N * sizeof(int), cudaMemcpyDeviceToDevice);
    k_fill<<<eb, 256>>>(adj, adj + E, cur, cola, nullptr, E);
    cudaMemsetAsync(cnt, 0, N * sizeof(int));
    k_count<<<eb, 256>>>(adjb + E, cnt, E);
    k_scan<<<1, 1024>>>(cnt, rpb, N);
    cudaMemcpyAsync(cur, rpb, N * sizeof(int), cudaMemcpyDeviceToDevice);
    k_fill<<<eb, 256>>>(adjb, adjb + E, cur, colb, perm, E);

    // ---- prep ----
    k_wprep<<<(6 * 16384 + 255) / 256, 256>>>(Wl, Wr, Wthi, Wtlo);
    k_split<<<(N * 32 + 255) / 256, 256>>>((const float4*)x, xhi, xlo, N * 32);
    k_mix_init<<<mixBlocks, 256>>>((const float4*)x, perm, mixr, mhi, mlo, N);

    // ---- layer 0 ----
    k_gemm_tc<<<gemmBlocks, 256, GEMM_SMEM>>>(xhi, xlo, Wl0h, Wl0l, Y, N);
    k_gemm_tc<<<gemmBlocks, 256, GEMM_SMEM>>>(xhi, xlo, Wr0h, Wr0l, R, N);
    k_gemm_tc<<<gemmBlocks, 256, GEMM_SMEM>>>(mhi, mlo, Wr0h, Wr0l, Z, N);
    k_aggmix<<<aggBlocks, 256>>>((const float4*)Y, rpa, cola, rpb, colb,
                                 (const float4*)Z, (const float4*)R, bl0, mixr,
                                 mhi, mlo, nullptr, hhi, hlo, N);

    // ---- layer 1 ----
    k_gemm_tc<<<gemmBlocks, 256, GEMM_SMEM>>>(hhi, hlo, Wl1h, Wl1l, Y, N);
    k_gemm_tc<<<gemmBlocks, 256, GEMM_SMEM>>>(hhi, hlo, Wr1h, Wr1l, R, N);
    k_gemm_tc<<<gemmBlocks, 256, GEMM_SMEM>>>(mhi, mlo, Wr1h, Wr1l, Z, N);
    k_aggmix<<<aggBlocks, 256>>>((const float4*)Y, rpa, cola, rpb, colb,
                                 (const float4*)Z, (const float4*)R, bl1, mixr,
                                 mhi, mlo, nullptr, hhi, hlo, N);

    // ---- layer 2 ----
    k_gemm_tc<<<gemmBlocks, 256, GEMM_SMEM>>>(hhi, hlo, Wl2h, Wl2l, Y, N);
    k_gemm_tc<<<gemmBlocks, 256, GEMM_SMEM>>>(mhi, mlo, Wr2h, Wr2l, Z, N);
    k_aggmix<<<aggBlocks, 256>>>((const float4*)Y, rpa, cola, rpb, colb,
                                 (const float4*)Z, nullptr, bl2, mixr,
                                 nullptr, nullptr, (float4*)mixF, nullptr, nullptr, N);

    // ---- logits ----
    k_logits<<<(N + 63) / 64, 256>>>(mixF, Wo, bo, (float*)d_out, N);
}

// round 4
// speedup vs baseline: 2.4650x; 1.2150x over previous
#include <cuda_runtime.h>
#include <cuda_bf16.h>
#include <cstdint>

#define NN 100000
#define EE 1600000

// ---------------- scratch ----------------
__device__ __align__(16) float g_Y[NN * 128];
__device__ __align__(16) float g_R[NN * 128];
__device__ __align__(16) float g_Z[NN * 128];
__device__ __align__(16) float g_aggA[NN * 128];
__device__ __align__(16) float g_aggB[NN * 128];
__device__ __align__(16) float g_mixF[NN * 128];
__device__ __align__(16) __nv_bfloat16 g_xhi[NN * 128];
__device__ __align__(16) __nv_bfloat16 g_xlo[NN * 128];
__device__ __align__(16) __nv_bfloat16 g_hhi[NN * 128];
__device__ __align__(16) __nv_bfloat16 g_hlo[NN * 128];
__device__ __align__(16) __nv_bfloat16 g_mhi[NN * 128];
__device__ __align__(16) __nv_bfloat16 g_mlo[NN * 128];
__device__ __align__(16) __nv_bfloat16 g_Wthi[6 * 128 * 128];
__device__ __align__(16) __nv_bfloat16 g_Wtlo[6 * 128 * 128];

__device__ int g_cntA[NN];
__device__ int g_cntB[NN];
__device__ int g_rpa[NN + 1];
__device__ int g_rpb[NN + 1];
__device__ int g_curA[NN];
__device__ int g_curB[NN];
__device__ int g_cola[EE];
__device__ int g_colb[EE];

// ---------------- helpers ----------------
__device__ __forceinline__ uint32_t pack_bf2(__nv_bfloat16 a, __nv_bfloat16 b) {
    __nv_bfloat162 t = __halves2bfloat162(a, b);
    return *reinterpret_cast<uint32_t*>(&t);
}

__device__ __forceinline__ void split_store4(float4 v, __nv_bfloat16* hi,
                                             __nv_bfloat16* lo, int off) {
    __nv_bfloat16 hx = __float2bfloat16(v.x);
    __nv_bfloat16 hy = __float2bfloat16(v.y);
    __nv_bfloat16 hz = __float2bfloat16(v.z);
    __nv_bfloat16 hw = __float2bfloat16(v.w);
    uint2 hv, lv;
    hv.x = pack_bf2(hx, hy);
    hv.y = pack_bf2(hz, hw);
    lv.x = pack_bf2(__float2bfloat16(v.x - __bfloat162float(hx)),
                    __float2bfloat16(v.y - __bfloat162float(hy)));
    lv.y = pack_bf2(__float2bfloat16(v.z - __bfloat162float(hz)),
                    __float2bfloat16(v.w - __bfloat162float(hw)));
    *reinterpret_cast<uint2*>(hi + off) = hv;
    *reinterpret_cast<uint2*>(lo + off) = lv;
}

__device__ __forceinline__ void mma_bf16(float* c, const uint32_t* a,
                                         uint32_t b0, uint32_t b1) {
    asm volatile(
        "mma.sync.aligned.m16n8k16.row.col.f32.bf16.bf16.f32 "
        "{%0,%1,%2,%3}, {%4,%5,%6,%7}, {%8,%9}, {%0,%1,%2,%3};"
        : "+f"(c[0]), "+f"(c[1]), "+f"(c[2]), "+f"(c[3])
        : "r"(a[0]), "r"(a[1]), "r"(a[2]), "r"(a[3]), "r"(b0), "r"(b1));
}

// ---------------- CSR build ----------------
__global__ void k_count(const int* __restrict__ dst, int* __restrict__ cnt, int E) {
    int i = blockIdx.x * blockDim.x + threadIdx.x;
    if (i < E) atomicAdd(&cnt[dst[i]], 1);
}

__global__ void k_scan(const int* __restrict__ cnt, int* __restrict__ rowptr, int n) {
    __shared__ int part[1024];
    int tid = threadIdx.x;
    int chunk = (n + 1023) >> 10;
    int s0 = tid * chunk;
    int s1 = min(s0 + chunk, n);
    int s = 0;
    for (int i = s0; i < s1; i++) s += cnt[i];
    part[tid] = s;
    __syncthreads();
    for (int off = 1; off < 1024; off <<= 1) {
        int v = part[tid];
        int u = (tid >= off) ? part[tid - off] : 0;
        __syncthreads();
        part[tid] = v + u;
        __syncthreads();
    }
    int run = (tid == 0) ? 0 : part[tid - 1];
    for (int i = s0; i < s1; i++) { rowptr[i] = run; run += cnt[i]; }
    if (tid == 1023) rowptr[n] = part[1023];
}

__global__ void k_fill(const int* __restrict__ src, const int* __restrict__ dst,
                       int* __restrict__ cursor, int* __restrict__ col,
                       const int* __restrict__ perm, int E) {
    int i = blockIdx.x * blockDim.x + threadIdx.x;
    if (i < E) {
        int d = dst[i];
        int pos = atomicAdd(&cursor[d], 1);
        int s = src[i];
        col[pos] = perm ? perm[s] : s;
    }
}

// ---------------- weight prep: transpose + bf16 split ----------------
__global__ void k_wprep(const float* __restrict__ Wl, const float* __restrict__ Wr,
                        __nv_bfloat16* __restrict__ Wthi, __nv_bfloat16* __restrict__ Wtlo) {
    int i = blockIdx.x * blockDim.x + threadIdx.x;
    if (i >= 6 * 16384) return;
    int m = i >> 14;
    int r = (i >> 7) & 127;
    int c = i & 127;
    const float* W = (m < 3) ? (Wl + m * 16384) : (Wr + (m - 3) * 16384);
    float v = W[r * 128 + c];
    __nv_bfloat16 h = __float2bfloat16(v);
    Wthi[m * 16384 + c * 128 + r] = h;
    Wtlo[m * 16384 + c * 128 + r] = __float2bfloat16(v - __bfloat162float(h));
}

// ---------------- x prep: split + mixup init in one pass ----------------
__global__ void k_prep_x(const float4* __restrict__ x, const int* __restrict__ perm,
                         const float* __restrict__ mixr,
                         __nv_bfloat16* __restrict__ xhi, __nv_bfloat16* __restrict__ xlo,
                         __nv_bfloat16* __restrict__ mhi, __nv_bfloat16* __restrict__ mlo,
                         int n) {
    int idx = blockIdx.x * blockDim.x + threadIdx.x;
    if (idx >= n * 32) return;
    int row = idx >> 5, lane = idx & 31;
    float4 a = __ldg(&x[idx]);
    split_store4(a, xhi, xlo, idx * 4);
    int p = __ldg(&perm[row]);
    float r = __ldg(mixr);
    float q = 1.0f - r;
    float4 b = __ldg(&x[p * 32 + lane]);
    float4 v = make_float4(r * a.x + q * b.x, r * a.y + q * b.y,
                           r * a.z + q * b.z, r * a.w + q * b.w);
    split_store4(v, mhi, mlo, idx * 4);
}

// ---------------- tensor-core GEMM (bf16x3) ----------------
#define PITCHW 36
__global__ __launch_bounds__(256) void k_gemm_tc(
    const __nv_bfloat16* __restrict__ Ahi, const __nv_bfloat16* __restrict__ Alo,
    const __nv_bfloat16* __restrict__ Wthi, const __nv_bfloat16* __restrict__ Wtlo,
    float* __restrict__ out, int M) {
    extern __shared__ uint32_t sm[];
    uint32_t* sWh = sm;
    uint32_t* sWl = sm + 128 * PITCHW;
    uint32_t* sAh = sm + 2 * 128 * PITCHW;
    uint32_t* sAl = sm + 3 * 128 * PITCHW;
    int tid = threadIdx.x;
    int w = tid >> 5, lane = tid & 31;
    int g = lane >> 2, tg = lane & 3;
    int m0 = (w & 3) * 32;
    int n0 = (w >> 2) * 64;
    int row0 = blockIdx.x * 128;

    float acc[2][8][4];
#pragma unroll
    for (int mi = 0; mi < 2; mi++)
#pragma unroll
        for (int j = 0; j < 8; j++)
#pragma unroll
            for (int q = 0; q < 4; q++) acc[mi][j][q] = 0.f;

    for (int kc = 0; kc < 2; kc++) {
        int k0 = kc * 64;
        if (kc) __syncthreads();
#pragma unroll
        for (int j = 0; j < 4; j++) {
            int f = tid + j * 256;
            int r = f >> 3, q = f & 7;
            size_t goff = (size_t)r * 256 + k0 * 2 + q * 16;
            uint4 wh = *(const uint4*)((const char*)Wthi + goff);
            uint4 wl = *(const uint4*)((const char*)Wtlo + goff);
            *(uint4*)&sWh[r * PITCHW + q * 4] = wh;
            *(uint4*)&sWl[r * PITCHW + q * 4] = wl;
            int rg = row0 + r;
            uint4 ah = make_uint4(0, 0, 0, 0), al = make_uint4(0, 0, 0, 0);
            if (rg < M) {
                size_t aoff = (size_t)rg * 256 + k0 * 2 + q * 16;
                ah = *(const uint4*)((const char*)Ahi + aoff);
                al = *(const uint4*)((const char*)Alo + aoff);
            }
            *(uint4*)&sAh[r * PITCHW + q * 4] = ah;
            *(uint4*)&sAl[r * PITCHW + q * 4] = al;
        }
        __syncthreads();
#pragma unroll
        for (int kb = 0; kb < 4; kb++) {
            int pa = kb * 8 + tg;
            uint32_t ah[2][4], al_[2][4];
#pragma unroll
            for (int mi = 0; mi < 2; mi++) {
                int rb = (m0 + mi * 16 + g) * PITCHW;
                ah[mi][0] = sAh[rb + pa];
                ah[mi][1] = sAh[rb + 8 * PITCHW + pa];
                ah[mi][2] = sAh[rb + pa + 4];
                ah[mi][3] = sAh[rb + 8 * PITCHW + pa + 4];
                al_[mi][0] = sAl[rb + pa];
                al_[mi][1] = sAl[rb + 8 * PITCHW + pa];
                al_[mi][2] = sAl[rb + pa + 4];
                al_[mi][3] = sAl[rb + 8 * PITCHW + pa + 4];
            }
#pragma unroll
            for (int j = 0; j < 8; j++) {
                int nb = (n0 + j * 8 + g) * PITCHW;
                uint32_t bh0 = sWh[nb + pa], bh1 = sWh[nb + pa + 4];
                uint32_t bl0 = sWl[nb + pa], bl1 = sWl[nb + pa + 4];
#pragma unroll
                for (int mi = 0; mi < 2; mi++) {
                    mma_bf16(acc[mi][j], ah[mi], bh0, bh1);
                    mma_bf16(acc[mi][j], ah[mi], bl0, bl1);
                    mma_bf16(acc[mi][j], al_[mi], bh0, bh1);
                }
            }
        }
    }
#pragma unroll
    for (int mi = 0; mi < 2; mi++) {
        int r1 = row0 + m0 + mi * 16 + g;
        int r2 = r1 + 8;
#pragma unroll
        for (int j = 0; j < 8; j++) {
            int cidx = n0 + j * 8 + 2 * tg;
            if (r1 < M)
                *(float2*)(out + (size_t)r1 * 128 + cidx) = make_float2(acc[mi][j][0], acc[mi][j][1]);
            if (r2 < M)
                *(float2*)(out + (size_t)r2 * 128 + cidx) = make_float2(acc[mi][j][2], acc[mi][j][3]);
        }
    }
}

// ---------------- dual gather (Y -> aggA, aggB) ----------------
__device__ __forceinline__ float4 gather_mean(const float4* __restrict__ Y,
                                              const int* __restrict__ rp,
                                              const int* __restrict__ col,
                                              int w, int lane) {
    int s = __ldg(&rp[w]), e = __ldg(&rp[w + 1]);
    float ax = 0.f, ay = 0.f, az = 0.f, aw = 0.f;
    int i = s;
    for (; i + 3 < e; i += 4) {
        int c0 = __ldg(&col[i + 0]);
        int c1 = __ldg(&col[i + 1]);
        int c2 = __ldg(&col[i + 2]);
        int c3 = __ldg(&col[i + 3]);
        float4 v0 = __ldg(&Y[c0 * 32 + lane]);
        float4 v1 = __ldg(&Y[c1 * 32 + lane]);
        float4 v2 = __ldg(&Y[c2 * 32 + lane]);
        float4 v3 = __ldg(&Y[c3 * 32 + lane]);
        ax += (v0.x + v1.x) + (v2.x + v3.x);
        ay += (v0.y + v1.y) + (v2.y + v3.y);
        az += (v0.z + v1.z) + (v2.z + v3.z);
        aw += (v0.w + v1.w) + (v2.w + v3.w);
    }
    for (; i < e; i++) {
        int c0 = __ldg(&col[i]);
        float4 v0 = __ldg(&Y[c0 * 32 + lane]);
        ax += v0.x; ay += v0.y; az += v0.z; aw += v0.w;
    }
    float inv = 1.0f / (float)max(e - s, 1);
    return make_float4(ax * inv, ay * inv, az * inv, aw * inv);
}

__global__ void k_gather2(const float4* __restrict__ Y,
                          const int* __restrict__ rpa, const int* __restrict__ cola,
                          const int* __restrict__ rpb, const int* __restrict__ colb,
                          float4* __restrict__ aggA, float4* __restrict__ aggB, int n) {
    int w = (blockIdx.x * blockDim.x + threadIdx.x) >> 5;
    int lane = threadIdx.x & 31;
    if (w >= n) return;
    aggA[w * 32 + lane] = gather_mean(Y, rpa, cola, w, lane);
    aggB[w * 32 + lane] = gather_mean(Y, rpb, colb, w, lane);
}

// ---------------- epilogue: mixup + h chain ----------------
__global__ void k_epi(const float4* __restrict__ aggA, const float4* __restrict__ aggB,
                      const float4* __restrict__ Z, const float4* __restrict__ R,
                      const float4* __restrict__ bias, const float* __restrict__ mixr,
                      __nv_bfloat16* __restrict__ mhi, __nv_bfloat16* __restrict__ mlo,
                      float4* __restrict__ mixF,
                      __nv_bfloat16* __restrict__ hhi, __nv_bfloat16* __restrict__ hlo,
                      int n32) {
    int idx = blockIdx.x * blockDim.x + threadIdx.x;
    if (idx >= n32) return;
    int lane = idx & 31;
    float4 aA = __ldg(&aggA[idx]);
    float4 aB = __ldg(&aggB[idx]);
    float4 z = __ldg(&Z[idx]);
    float4 b = __ldg(&bias[lane]);
    float r = __ldg(mixr);
    float q = 1.0f - r;
    float4 sA = make_float4(fmaxf(aA.x + z.x + b.x, 0.f), fmaxf(aA.y + z.y + b.y, 0.f),
                            fmaxf(aA.z + z.z + b.z, 0.f), fmaxf(aA.w + z.w + b.w, 0.f));
    float4 sB = make_float4(fmaxf(aB.x + z.x + b.x, 0.f), fmaxf(aB.y + z.y + b.y, 0.f),
                            fmaxf(aB.z + z.z + b.z, 0.f), fmaxf(aB.w + z.w + b.w, 0.f));
    float4 mix = make_float4(r * sA.x + q * sB.x, r * sA.y + q * sB.y,
                             r * sA.z + q * sB.z, r * sA.w + q * sB.w);
    if (mixF) mixF[idx] = mix;
    else split_store4(mix, mhi, mlo, idx * 4);
    if (hhi) {
        float4 rv = __ldg(&R[idx]);
        float4 h = make_float4(
            fmaxf(aA.x + rv.x + b.x, 0.f), fmaxf(aA.y + rv.y + b.y, 0.f),
            fmaxf(aA.z + rv.z + b.z, 0.f), fmaxf(aA.w + rv.w + b.w, 0.f));
        split_store4(h, hhi, hlo, idx * 4);
    }
}

// ---------------- logits + log_softmax ----------------
__global__ __launch_bounds__(256) void k_logits(
    const float* __restrict__ X, const float* __restrict__ Wo,
    const float* __restrict__ bo, float* __restrict__ out, int n) {
    __shared__ float Ws[128 * 40];
    __shared__ float bs[40];
    int tid = threadIdx.x;
    for (int i = tid; i < 128 * 40; i += 256) Ws[i] = Wo[i];
    if (tid < 40) bs[tid] = bo[tid];
    __syncthreads();

    int row = blockIdx.x * 64 + (tid >> 2);
    int row_c = min(row, n - 1);
    int cg = (tid & 3) * 10;

    float acc[10];
#pragma unroll
    for (int j = 0; j < 10; j++) acc[j] = bs[cg + j];

    const float4* xr = (const float4*)(X + (size_t)row_c * 128);
#pragma unroll 8
    for (int k4 = 0; k4 < 32; k4++) {
        float4 xv = __ldg(&xr[k4]);
        float xs[4] = { xv.x, xv.y, xv.z, xv.w };
#pragma unroll
        for (int kk = 0; kk < 4; kk++) {
            int k = k4 * 4 + kk;
#pragma unroll
            for (int j = 0; j < 10; j++)
                acc[j] = fmaf(xs[kk], Ws[k * 40 + cg + j], acc[j]);
        }
    }
    float m = acc[0];
#pragma unroll
    for (int j = 1; j < 10; j++) m = fmaxf(m, acc[j]);
    m = fmaxf(m, __shfl_xor_sync(0xffffffffu, m, 1));
    m = fmaxf(m, __shfl_xor_sync(0xffffffffu, m, 2));
    float s = 0.f;
#pragma unroll
    for (int j = 0; j < 10; j++) s += expf(acc[j] - m);
    s += __shfl_xor_sync(0xffffffffu, s, 1);
    s += __shfl_xor_sync(0xffffffffu, s, 2);
    float lse = m + logf(s);
    if (row < n) {
#pragma unroll
        for (int j = 0; j < 10; j++) out[row * 40 + cg + j] = acc[j] - lse;
    }
}

// ---------------- launch ----------------
extern "C" void kernel_launch(void* const* d_in, const int* in_sizes, int n_in,
                              void* d_out, int out_size) {
    const float* x    = (const float*)d_in[0];
    const float* Wl   = (const float*)d_in[1];
    const float* bl   = (const float*)d_in[2];
    const float* Wr   = (const float*)d_in[3];
    const float* Wo   = (const float*)d_in[4];
    const float* bo   = (const float*)d_in[5];
    const float* mixr = (const float*)d_in[6];
    const int*   adj  = (const int*)d_in[7];
    const int*   adjb = (const int*)d_in[8];
    const int*   perm = (const int*)d_in[9];

    int N = in_sizes[0] / 128;
    int E = in_sizes[7] / 2;

    float *Y, *R, *Z, *aggA, *aggB, *mixF;
    __nv_bfloat16 *xhi, *xlo, *hhi, *hlo, *mhi, *mlo, *Wthi, *Wtlo;
    int *cntA, *cntB, *rpa, *rpb, *curA, *curB, *cola, *colb;
    cudaGetSymbolAddress((void**)&Y, g_Y);
    cudaGetSymbolAddress((void**)&R, g_R);
    cudaGetSymbolAddress((void**)&Z, g_Z);
    cudaGetSymbolAddress((void**)&aggA, g_aggA);
    cudaGetSymbolAddress((void**)&aggB, g_aggB);
    cudaGetSymbolAddress((void**)&mixF, g_mixF);
    cudaGetSymbolAddress((void**)&xhi, g_xhi);
    cudaGetSymbolAddress((void**)&xlo, g_xlo);
    cudaGetSymbolAddress((void**)&hhi, g_hhi);
    cudaGetSymbolAddress((void**)&hlo, g_hlo);
    cudaGetSymbolAddress((void**)&mhi, g_mhi);
    cudaGetSymbolAddress((void**)&mlo, g_mlo);
    cudaGetSymbolAddress((void**)&Wthi, g_Wthi);
    cudaGetSymbolAddress((void**)&Wtlo, g_Wtlo);
    cudaGetSymbolAddress((void**)&cntA, g_cntA);
    cudaGetSymbolAddress((void**)&cntB, g_cntB);
    cudaGetSymbolAddress((void**)&rpa, g_rpa);
    cudaGetSymbolAddress((void**)&rpb, g_rpb);
    cudaGetSymbolAddress((void**)&curA, g_curA);
    cudaGetSymbolAddress((void**)&curB, g_curB);
    cudaGetSymbolAddress((void**)&cola, g_cola);
    cudaGetSymbolAddress((void**)&colb, g_colb);

    static cudaStream_t s1 = nullptr, s2 = nullptr, s3 = nullptr;
    static cudaEvent_t ev0, evPrep, evCSRa, evCSRb, evRZ0, evHM1, evRZ1, evHM2, evZ2;
    static int inited = 0;
    const int GEMM_SMEM = 4 * 128 * PITCHW * 4;
    if (!inited) {
        cudaFuncSetAttribute(k_gemm_tc, cudaFuncAttributeMaxDynamicSharedMemorySize, GEMM_SMEM);
        cudaStreamCreateWithFlags(&s1, cudaStreamNonBlocking);
        cudaStreamCreateWithFlags(&s2, cudaStreamNonBlocking);
        cudaStreamCreateWithFlags(&s3, cudaStreamNonBlocking);
        cudaEventCreateWithFlags(&ev0, cudaEventDisableTiming);
        cudaEventCreateWithFlags(&evPrep, cudaEventDisableTiming);
        cudaEventCreateWithFlags(&evCSRa, cudaEventDisableTiming);
        cudaEventCreateWithFlags(&evCSRb, cudaEventDisableTiming);
        cudaEventCreateWithFlags(&evRZ0, cudaEventDisableTiming);
        cudaEventCreateWithFlags(&evHM1, cudaEventDisableTiming);
        cudaEventCreateWithFlags(&evRZ1, cudaEventDisableTiming);
        cudaEventCreateWithFlags(&evHM2, cudaEventDisableTiming);
        cudaEventCreateWithFlags(&evZ2, cudaEventDisableTiming);
        inited = 1;
    }

    int eb = (E + 255) / 256;
    int aggBlocks = (N + 7) / 8;
    int gemmBlocks = (N + 127) / 128;
    int n32 = N * 32;
    int epiBlocks = (n32 + 255) / 256;

    const float4* bl0 = (const float4*)bl;
    const float4* bl1 = (const float4*)(bl + 128);
    const float4* bl2 = (const float4*)(bl + 256);
    __nv_bfloat16* Wl0h = Wthi + 0 * 16384; __nv_bfloat16* Wl0l = Wtlo + 0 * 16384;
    __nv_bfloat16* Wl1h = Wthi + 1 * 16384; __nv_bfloat16* Wl1l = Wtlo + 1 * 16384;
    __nv_bfloat16* Wl2h = Wthi + 2 * 16384; __nv_bfloat16* Wl2l = Wtlo + 2 * 16384;
    __nv_bfloat16* Wr0h = Wthi + 3 * 16384; __nv_bfloat16* Wr0l = Wtlo + 3 * 16384;
    __nv_bfloat16* Wr1h = Wthi + 4 * 16384; __nv_bfloat16* Wr1l = Wtlo + 4 * 16384;
    __nv_bfloat16* Wr2h = Wthi + 5 * 16384; __nv_bfloat16* Wr2l = Wtlo + 5 * 16384;

    // ---- fork: CSR builds on s1/s2 ----
    cudaEventRecord(ev0, 0);
    cudaStreamWaitEvent(s1, ev0, 0);
    cudaStreamWaitEvent(s2, ev0, 0);
    cudaStreamWaitEvent(s3, ev0, 0);

    cudaMemsetAsync(cntA, 0, N * sizeof(int), s1);
    k_count<<<eb, 256, 0, s1>>>(adj + E, cntA, E);
    k_scan<<<1, 1024, 0, s1>>>(cntA, rpa, N);
    cudaMemcpyAsync(curA, rpa, N * sizeof(int), cudaMemcpyDeviceToDevice, s1);
    k_fill<<<eb, 256, 0, s1>>>(adj, adj + E, curA, cola, nullptr, E);
    cudaEventRecord(evCSRa, s1);

    cudaMemsetAsync(cntB, 0, N * sizeof(int), s2);
    k_count<<<eb, 256, 0, s2>>>(adjb + E, cntB, E);
    k_scan<<<1, 1024, 0, s2>>>(cntB, rpb, N);
    cudaMemcpyAsync(curB, rpb, N * sizeof(int), cudaMemcpyDeviceToDevice, s2);
    k_fill<<<eb, 256, 0, s2>>>(adjb, adjb + E, curB, colb, perm, E);
    cudaEventRecord(evCSRb, s2);

    // ---- prep on main ----
    k_wprep<<<(6 * 16384 + 255) / 256, 256>>>(Wl, Wr, Wthi, Wtlo);
    k_prep_x<<<epiBlocks, 256>>>((const float4*)x, perm, mixr, xhi, xlo, mhi, mlo, N);
    cudaEventRecord(evPrep, 0);

    // ---- layer 0 ----
    // side: R0 = x@Wr0, Z0 = m0@Wr0
    cudaStreamWaitEvent(s3, evPrep, 0);
    k_gemm_tc<<<gemmBlocks, 256, GEMM_SMEM, s3>>>(xhi, xlo, Wr0h, Wr0l, R, N);
    k_gemm_tc<<<gemmBlocks, 256, GEMM_SMEM, s3>>>(mhi, mlo, Wr0h, Wr0l, Z, N);
    cudaEventRecord(evRZ0, s3);
    // main: Y0 = x@Wl0, gathers
    k_gemm_tc<<<gemmBlocks, 256, GEMM_SMEM>>>(xhi, xlo, Wl0h, Wl0l, Y, N);
    cudaStreamWaitEvent(0, evCSRa, 0);
    cudaStreamWaitEvent(0, evCSRb, 0);
    k_gather2<<<aggBlocks, 256>>>((const float4*)Y, rpa, cola, rpb, colb,
                                  (float4*)aggA, (float4*)aggB, N);
    cudaStreamWaitEvent(0, evRZ0, 0);
    k_epi<<<epiBlocks, 256>>>((const float4*)aggA, (const float4*)aggB,
                              (const float4*)Z, (const float4*)R, bl0, mixr,
                              mhi, mlo, nullptr, hhi, hlo, n32);
    cudaEventRecord(evHM1, 0);

    // ---- layer 1 ----
    cudaStreamWaitEvent(s3, evHM1, 0);
    k_gemm_tc<<<gemmBlocks, 256, GEMM_SMEM, s3>>>(hhi, hlo, Wr1h, Wr1l, R, N);
    k_gemm_tc<<<gemmBlocks, 256, GEMM_SMEM, s3>>>(mhi, mlo, Wr1h, Wr1l, Z, N);
    cudaEventRecord(evRZ1, s3);
    k_gemm_tc<<<gemmBlocks, 256, GEMM_SMEM>>>(hhi, hlo, Wl1h, Wl1l, Y, N);
    k_gather2<<<aggBlocks, 256>>>((const float4*)Y, rpa, cola, rpb, colb,
                                  (float4*)aggA, (float4*)aggB, N);
    cudaStreamWaitEvent(0, evRZ1, 0);
    k_epi<<<epiBlocks, 256>>>((const float4*)aggA, (const float4*)aggB,
                              (const float4*)Z, (const float4*)R, bl1, mixr,
                              mhi, mlo, nullptr, hhi, hlo, n32);
    cudaEventRecord(evHM2, 0);

    // ---- layer 2 (no h chain) ----
    cudaStreamWaitEvent(s3, evHM2, 0);
    k_gemm_tc<<<gemmBlocks, 256, GEMM_SMEM, s3>>>(mhi, mlo, Wr2h, Wr2l, Z, N);
    cudaEventRecord(evZ2, s3);
    k_gemm_tc<<<gemmBlocks, 256, GEMM_SMEM>>>(hhi, hlo, Wl2h, Wl2l, Y, N);
    k_gather2<<<aggBlocks, 256>>>((const float4*)Y, rpa, cola, rpb, colb,
                                  (float4*)aggA, (float4*)aggB, N);
    cudaStreamWaitEvent(0, evZ2, 0);
    k_epi<<<epiBlocks, 256>>>((const float4*)aggA, (const float4*)aggB,
                              (const float4*)Z, nullptr, bl2, mixr,
                              nullptr, nullptr, (float4*)mixF, nullptr, nullptr, n32);

    // ---- logits ----
    k_logits<<<(N + 63) / 64, 256>>>(mixF, Wo, bo, (float*)d_out, N);
}

// round 5
// speedup vs baseline: 2.7082x; 1.0987x over previous
#include <cuda_runtime.h>
#include <cuda_bf16.h>
#include <cstdint>

#define NN 100000
#define EE 1600000

// ---------------- scratch ----------------
__device__ __align__(16) __nv_bfloat16 g_Ybf[NN * 128];
__device__ __align__(16) float g_R[NN * 128];
__device__ __align__(16) float g_Z[NN * 128];
__device__ __align__(16) float g_aggA[NN * 128];
__device__ __align__(16) float g_aggB[NN * 128];
__device__ __align__(16) float g_mixF[NN * 128];
__device__ __align__(16) __nv_bfloat16 g_xhi[NN * 128];
__device__ __align__(16) __nv_bfloat16 g_xlo[NN * 128];
__device__ __align__(16) __nv_bfloat16 g_hhi[NN * 128];
__device__ __align__(16) __nv_bfloat16 g_hlo[NN * 128];
__device__ __align__(16) __nv_bfloat16 g_mhi[NN * 128];
__device__ __align__(16) __nv_bfloat16 g_mlo[NN * 128];
__device__ __align__(16) __nv_bfloat16 g_Wthi[6 * 128 * 128];
__device__ __align__(16) __nv_bfloat16 g_Wtlo[6 * 128 * 128];

__device__ int g_cntA[NN];
__device__ int g_cntB[NN];
__device__ int g_rpa[NN + 1];
__device__ int g_rpb[NN + 1];
__device__ int g_curA[NN];
__device__ int g_curB[NN];
__device__ int g_cola[EE];
__device__ int g_colb[EE];

// ---------------- helpers ----------------
__device__ __forceinline__ uint32_t pack_bf2(__nv_bfloat16 a, __nv_bfloat16 b) {
    __nv_bfloat162 t = __halves2bfloat162(a, b);
    return *reinterpret_cast<uint32_t*>(&t);
}

__device__ __forceinline__ void split_store4(float4 v, __nv_bfloat16* hi,
                                             __nv_bfloat16* lo, int off) {
    __nv_bfloat16 hx = __float2bfloat16(v.x);
    __nv_bfloat16 hy = __float2bfloat16(v.y);
    __nv_bfloat16 hz = __float2bfloat16(v.z);
    __nv_bfloat16 hw = __float2bfloat16(v.w);
    uint2 hv, lv;
    hv.x = pack_bf2(hx, hy);
    hv.y = pack_bf2(hz, hw);
    lv.x = pack_bf2(__float2bfloat16(v.x - __bfloat162float(hx)),
                    __float2bfloat16(v.y - __bfloat162float(hy)));
    lv.y = pack_bf2(__float2bfloat16(v.z - __bfloat162float(hz)),
                    __float2bfloat16(v.w - __bfloat162float(hw)));
    *reinterpret_cast<uint2*>(hi + off) = hv;
    *reinterpret_cast<uint2*>(lo + off) = lv;
}

__device__ __forceinline__ void mma_bf16(float* c, const uint32_t* a,
                                         uint32_t b0, uint32_t b1) {
    asm volatile(
        "mma.sync.aligned.m16n8k16.row.col.f32.bf16.bf16.f32 "
        "{%0,%1,%2,%3}, {%4,%5,%6,%7}, {%8,%9}, {%0,%1,%2,%3};"
        : "+f"(c[0]), "+f"(c[1]), "+f"(c[2]), "+f"(c[3])
        : "r"(a[0]), "r"(a[1]), "r"(a[2]), "r"(a[3]), "r"(b0), "r"(b1));
}

// ---------------- CSR build ----------------
__global__ void k_count(const int* __restrict__ dst, int* __restrict__ cnt, int E) {
    int i = blockIdx.x * blockDim.x + threadIdx.x;
    if (i < E) atomicAdd(&cnt[dst[i]], 1);
}

__global__ void k_scan(const int* __restrict__ cnt, int* __restrict__ rowptr, int n) {
    __shared__ int part[1024];
    int tid = threadIdx.x;
    int chunk = (n + 1023) >> 10;
    int s0 = tid * chunk;
    int s1 = min(s0 + chunk, n);
    int s = 0;
    for (int i = s0; i < s1; i++) s += cnt[i];
    part[tid] = s;
    __syncthreads();
    for (int off = 1; off < 1024; off <<= 1) {
        int v = part[tid];
        int u = (tid >= off) ? part[tid - off] : 0;
        __syncthreads();
        part[tid] = v + u;
        __syncthreads();
    }
    int run = (tid == 0) ? 0 : part[tid - 1];
    for (int i = s0; i < s1; i++) { rowptr[i] = run; run += cnt[i]; }
    if (tid == 1023) rowptr[n] = part[1023];
}

__global__ void k_fill(const int* __restrict__ src, const int* __restrict__ dst,
                       int* __restrict__ cursor, int* __restrict__ col,
                       const int* __restrict__ perm, int E) {
    int i = blockIdx.x * blockDim.x + threadIdx.x;
    if (i < E) {
        int d = dst[i];
        int pos = atomicAdd(&cursor[d], 1);
        int s = src[i];
        col[pos] = perm ? perm[s] : s;
    }
}

// ---------------- weight prep: transpose + bf16 split ----------------
__global__ void k_wprep(const float* __restrict__ Wl, const float* __restrict__ Wr,
                        __nv_bfloat16* __restrict__ Wthi, __nv_bfloat16* __restrict__ Wtlo) {
    int i = blockIdx.x * blockDim.x + threadIdx.x;
    if (i >= 6 * 16384) return;
    int m = i >> 14;
    int r = (i >> 7) & 127;
    int c = i & 127;
    const float* W = (m < 3) ? (Wl + m * 16384) : (Wr + (m - 3) * 16384);
    float v = W[r * 128 + c];
    __nv_bfloat16 h = __float2bfloat16(v);
    Wthi[m * 16384 + c * 128 + r] = h;
    Wtlo[m * 16384 + c * 128 + r] = __float2bfloat16(v - __bfloat162float(h));
}

// ---------------- x prep: split + mixup init in one pass ----------------
__global__ void k_prep_x(const float4* __restrict__ x, const int* __restrict__ perm,
                         const float* __restrict__ mixr,
                         __nv_bfloat16* __restrict__ xhi, __nv_bfloat16* __restrict__ xlo,
                         __nv_bfloat16* __restrict__ mhi, __nv_bfloat16* __restrict__ mlo,
                         int n) {
    int idx = blockIdx.x * blockDim.x + threadIdx.x;
    if (idx >= n * 32) return;
    int row = idx >> 5, lane = idx & 31;
    float4 a = __ldg(&x[idx]);
    split_store4(a, xhi, xlo, idx * 4);
    int p = __ldg(&perm[row]);
    float r = __ldg(mixr);
    float q = 1.0f - r;
    float4 b = __ldg(&x[p * 32 + lane]);
    float4 v = make_float4(r * a.x + q * b.x, r * a.y + q * b.y,
                           r * a.z + q * b.z, r * a.w + q * b.w);
    split_store4(v, mhi, mlo, idx * 4);
}

// ---------------- tensor-core GEMM (bf16x3), fp32 or bf16 output ----------------
#define PITCHW 36
template <int BFOUT>
__global__ __launch_bounds__(256) void k_gemm_tc(
    const __nv_bfloat16* __restrict__ Ahi, const __nv_bfloat16* __restrict__ Alo,
    const __nv_bfloat16* __restrict__ Wthi, const __nv_bfloat16* __restrict__ Wtlo,
    float* __restrict__ out, __nv_bfloat16* __restrict__ outbf, int M) {
    extern __shared__ uint32_t sm[];
    uint32_t* sWh = sm;
    uint32_t* sWl = sm + 128 * PITCHW;
    uint32_t* sAh = sm + 2 * 128 * PITCHW;
    uint32_t* sAl = sm + 3 * 128 * PITCHW;
    int tid = threadIdx.x;
    int w = tid >> 5, lane = tid & 31;
    int g = lane >> 2, tg = lane & 3;
    int m0 = (w & 3) * 32;
    int n0 = (w >> 2) * 64;
    int row0 = blockIdx.x * 128;

    float acc[2][8][4];
#pragma unroll
    for (int mi = 0; mi < 2; mi++)
#pragma unroll
        for (int j = 0; j < 8; j++)
#pragma unroll
            for (int q = 0; q < 4; q++) acc[mi][j][q] = 0.f;

    for (int kc = 0; kc < 2; kc++) {
        int k0 = kc * 64;
        if (kc) __syncthreads();
#pragma unroll
        for (int j = 0; j < 4; j++) {
            int f = tid + j * 256;
            int r = f >> 3, q = f & 7;
            size_t goff = (size_t)r * 256 + k0 * 2 + q * 16;
            uint4 wh = *(const uint4*)((const char*)Wthi + goff);
            uint4 wl = *(const uint4*)((const char*)Wtlo + goff);
            *(uint4*)&sWh[r * PITCHW + q * 4] = wh;
            *(uint4*)&sWl[r * PITCHW + q * 4] = wl;
            int rg = row0 + r;
            uint4 ah = make_uint4(0, 0, 0, 0), al = make_uint4(0, 0, 0, 0);
            if (rg < M) {
                size_t aoff = (size_t)rg * 256 + k0 * 2 + q * 16;
                ah = *(const uint4*)((const char*)Ahi + aoff);
                al = *(const uint4*)((const char*)Alo + aoff);
            }
            *(uint4*)&sAh[r * PITCHW + q * 4] = ah;
            *(uint4*)&sAl[r * PITCHW + q * 4] = al;
        }
        __syncthreads();
#pragma unroll
        for (int kb = 0; kb < 4; kb++) {
            int pa = kb * 8 + tg;
            uint32_t ah[2][4], al_[2][4];
#pragma unroll
            for (int mi = 0; mi < 2; mi++) {
                int rb = (m0 + mi * 16 + g) * PITCHW;
                ah[mi][0] = sAh[rb + pa];
                ah[mi][1] = sAh[rb + 8 * PITCHW + pa];
                ah[mi][2] = sAh[rb + pa + 4];
                ah[mi][3] = sAh[rb + 8 * PITCHW + pa + 4];
                al_[mi][0] = sAl[rb + pa];
                al_[mi][1] = sAl[rb + 8 * PITCHW + pa];
                al_[mi][2] = sAl[rb + pa + 4];
                al_[mi][3] = sAl[rb + 8 * PITCHW + pa + 4];
            }
#pragma unroll
            for (int j = 0; j < 8; j++) {
                int nb = (n0 + j * 8 + g) * PITCHW;
                uint32_t bh0 = sWh[nb + pa], bh1 = sWh[nb + pa + 4];
                uint32_t bl0 = sWl[nb + pa], bl1 = sWl[nb + pa + 4];
#pragma unroll
                for (int mi = 0; mi < 2; mi++) {
                    mma_bf16(acc[mi][j], ah[mi], bh0, bh1);
                    mma_bf16(acc[mi][j], ah[mi], bl0, bl1);
                    mma_bf16(acc[mi][j], al_[mi], bh0, bh1);
                }
            }
        }
    }
#pragma unroll
    for (int mi = 0; mi < 2; mi++) {
        int r1 = row0 + m0 + mi * 16 + g;
        int r2 = r1 + 8;
#pragma unroll
        for (int j = 0; j < 8; j++) {
            int cidx = n0 + j * 8 + 2 * tg;
            if (BFOUT) {
                if (r1 < M)
                    *(__nv_bfloat162*)(outbf + (size_t)r1 * 128 + cidx) =
                        __floats2bfloat162_rn(acc[mi][j][0], acc[mi][j][1]);
                if (r2 < M)
                    *(__nv_bfloat162*)(outbf + (size_t)r2 * 128 + cidx) =
                        __floats2bfloat162_rn(acc[mi][j][2], acc[mi][j][3]);
            } else {
                if (r1 < M)
                    *(float2*)(out + (size_t)r1 * 128 + cidx) = make_float2(acc[mi][j][0], acc[mi][j][1]);
                if (r2 < M)
                    *(float2*)(out + (size_t)r2 * 128 + cidx) = make_float2(acc[mi][j][2], acc[mi][j][3]);
            }
        }
    }
}

// ---------------- dual gather from bf16 Y (Y -> aggA, aggB) ----------------
// Row = 128 bf16 = 256B; lane handles 4 consecutive bf16 (uint2 load).
__device__ __forceinline__ float4 gather_mean_bf(const uint2* __restrict__ Y,
                                                 const int* __restrict__ rp,
                                                 const int* __restrict__ col,
                                                 int w, int lane) {
    int s = __ldg(&rp[w]), e = __ldg(&rp[w + 1]);
    float ax = 0.f, ay = 0.f, az = 0.f, aw = 0.f;
    int i = s;
    for (; i + 3 < e; i += 4) {
        int c0 = __ldg(&col[i + 0]);
        int c1 = __ldg(&col[i + 1]);
        int c2 = __ldg(&col[i + 2]);
        int c3 = __ldg(&col[i + 3]);
        uint2 u0 = __ldg(&Y[c0 * 32 + lane]);
        uint2 u1 = __ldg(&Y[c1 * 32 + lane]);
        uint2 u2 = __ldg(&Y[c2 * 32 + lane]);
        uint2 u3 = __ldg(&Y[c3 * 32 + lane]);
        float2 a0 = __bfloat1622float2(*(__nv_bfloat162*)&u0.x);
        float2 b0 = __bfloat1622float2(*(__nv_bfloat162*)&u0.y);
        float2 a1 = __bfloat1622float2(*(__nv_bfloat162*)&u1.x);
        float2 b1 = __bfloat1622float2(*(__nv_bfloat162*)&u1.y);
        float2 a2 = __bfloat1622float2(*(__nv_bfloat162*)&u2.x);
        float2 b2 = __bfloat1622float2(*(__nv_bfloat162*)&u2.y);
        float2 a3 = __bfloat1622float2(*(__nv_bfloat162*)&u3.x);
        float2 b3 = __bfloat1622float2(*(__nv_bfloat162*)&u3.y);
        ax += (a0.x + a1.x) + (a2.x + a3.x);
        ay += (a0.y + a1.y) + (a2.y + a3.y);
        az += (b0.x + b1.x) + (b2.x + b3.x);
        aw += (b0.y + b1.y) + (b2.y + b3.y);
    }
    for (; i < e; i++) {
        int c0 = __ldg(&col[i]);
        uint2 u0 = __ldg(&Y[c0 * 32 + lane]);
        float2 a0 = __bfloat1622float2(*(__nv_bfloat162*)&u0.x);
        float2 b0 = __bfloat1622float2(*(__nv_bfloat162*)&u0.y);
        ax += a0.x; ay += a0.y; az += b0.x; aw += b0.y;
    }
    float inv = 1.0f / (float)max(e - s, 1);
    return make_float4(ax * inv, ay * inv, az * inv, aw * inv);
}

__global__ void k_gather2(const uint2* __restrict__ Y,
                          const int* __restrict__ rpa, const int* __restrict__ cola,
                          const int* __restrict__ rpb, const int* __restrict__ colb,
                          float4* __restrict__ aggA, float4* __restrict__ aggB, int n) {
    int w = (blockIdx.x * blockDim.x + threadIdx.x) >> 5;
    int lane = threadIdx.x & 31;
    if (w >= n) return;
    aggA[w * 32 + lane] = gather_mean_bf(Y, rpa, cola, w, lane);
    aggB[w * 32 + lane] = gather_mean_bf(Y, rpb, colb, w, lane);
}

// ---------------- epilogue: mixup + h chain ----------------
__global__ void k_epi(const float4* __restrict__ aggA, const float4* __restrict__ aggB,
                      const float4* __restrict__ Z, const float4* __restrict__ R,
                      const float4* __restrict__ bias, const float* __restrict__ mixr,
                      __nv_bfloat16* __restrict__ mhi, __nv_bfloat16* __restrict__ mlo,
                      float4* __restrict__ mixF,
                      __nv_bfloat16* __restrict__ hhi, __nv_bfloat16* __restrict__ hlo,
                      int n32) {
    int idx = blockIdx.x * blockDim.x + threadIdx.x;
    if (idx >= n32) return;
    int lane = idx & 31;
    float4 aA = __ldg(&aggA[idx]);
    float4 aB = __ldg(&aggB[idx]);
    float4 z = __ldg(&Z[idx]);
    float4 b = __ldg(&bias[lane]);
    float r = __ldg(mixr);
    float q = 1.0f - r;
    float4 sA = make_float4(fmaxf(aA.x + z.x + b.x, 0.f), fmaxf(aA.y + z.y + b.y, 0.f),
                            fmaxf(aA.z + z.z + b.z, 0.f), fmaxf(aA.w + z.w + b.w, 0.f));
    float4 sB = make_float4(fmaxf(aB.x + z.x + b.x, 0.f), fmaxf(aB.y + z.y + b.y, 0.f),
                            fmaxf(aB.z + z.z + b.z, 0.f), fmaxf(aB.w + z.w + b.w, 0.f));
    float4 mix = make_float4(r * sA.x + q * sB.x, r * sA.y + q * sB.y,
                             r * sA.z + q * sB.z, r * sA.w + q * sB.w);
    if (mixF) mixF[idx] = mix;
    else split_store4(mix, mhi, mlo, idx * 4);
    if (hhi) {
        float4 rv = __ldg(&R[idx]);
        float4 h = make_float4(
            fmaxf(aA.x + rv.x + b.x, 0.f), fmaxf(aA.y + rv.y + b.y, 0.f),
            fmaxf(aA.z + rv.z + b.z, 0.f), fmaxf(aA.w + rv.w + b.w, 0.f));
        split_store4(h, hhi, hlo, idx * 4);
    }
}

// ---------------- logits + log_softmax ----------------
__global__ __launch_bounds__(256) void k_logits(
    const float* __restrict__ X, const float* __restrict__ Wo,
    const float* __restrict__ bo, float* __restrict__ out, int n) {
    __shared__ float Ws[128 * 40];
    __shared__ float bs[40];
    int tid = threadIdx.x;
    for (int i = tid; i < 128 * 40; i += 256) Ws[i] = Wo[i];
    if (tid < 40) bs[tid] = bo[tid];
    __syncthreads();

    int row = blockIdx.x * 64 + (tid >> 2);
    int row_c = min(row, n - 1);
    int cg = (tid & 3) * 10;

    float acc[10];
#pragma unroll
    for (int j = 0; j < 10; j++) acc[j] = bs[cg + j];

    const float4* xr = (const float4*)(X + (size_t)row_c * 128);
#pragma unroll 8
    for (int k4 = 0; k4 < 32; k4++) {
        float4 xv = __ldg(&xr[k4]);
        float xs[4] = { xv.x, xv.y, xv.z, xv.w };
#pragma unroll
        for (int kk = 0; kk < 4; kk++) {
            int k = k4 * 4 + kk;
#pragma unroll
            for (int j = 0; j < 10; j++)
                acc[j] = fmaf(xs[kk], Ws[k * 40 + cg + j], acc[j]);
        }
    }
    float m = acc[0];
#pragma unroll
    for (int j = 1; j < 10; j++) m = fmaxf(m, acc[j]);
    m = fmaxf(m, __shfl_xor_sync(0xffffffffu, m, 1));
    m = fmaxf(m, __shfl_xor_sync(0xffffffffu, m, 2));
    float s = 0.f;
#pragma unroll
    for (int j = 0; j < 10; j++) s += expf(acc[j] - m);
    s += __shfl_xor_sync(0xffffffffu, s, 1);
    s += __shfl_xor_sync(0xffffffffu, s, 2);
    float lse = m + logf(s);
    if (row < n) {
#pragma unroll
        for (int j = 0; j < 10; j++) out[row * 40 + cg + j] = acc[j] - lse;
    }
}

// ---------------- launch ----------------
extern "C" void kernel_launch(void* const* d_in, const int* in_sizes, int n_in,
                              void* d_out, int out_size) {
    const float* x    = (const float*)d_in[0];
    const float* Wl   = (const float*)d_in[1];
    const float* bl   = (const float*)d_in[2];
    const float* Wr   = (const float*)d_in[3];
    const float* Wo   = (const float*)d_in[4];
    const float* bo   = (const float*)d_in[5];
    const float* mixr = (const float*)d_in[6];
    const int*   adj  = (const int*)d_in[7];
    const int*   adjb = (const int*)d_in[8];
    const int*   perm = (const int*)d_in[9];

    int N = in_sizes[0] / 128;
    int E = in_sizes[7] / 2;

    float *R, *Z, *aggA, *aggB, *mixF;
    __nv_bfloat16 *Ybf, *xhi, *xlo, *hhi, *hlo, *mhi, *mlo, *Wthi, *Wtlo;
    int *cntA, *cntB, *rpa, *rpb, *curA, *curB, *cola, *colb;
    cudaGetSymbolAddress((void**)&Ybf, g_Ybf);
    cudaGetSymbolAddress((void**)&R, g_R);
    cudaGetSymbolAddress((void**)&Z, g_Z);
    cudaGetSymbolAddress((void**)&aggA, g_aggA);
    cudaGetSymbolAddress((void**)&aggB, g_aggB);
    cudaGetSymbolAddress((void**)&mixF, g_mixF);
    cudaGetSymbolAddress((void**)&xhi, g_xhi);
    cudaGetSymbolAddress((void**)&xlo, g_xlo);
    cudaGetSymbolAddress((void**)&hhi, g_hhi);
    cudaGetSymbolAddress((void**)&hlo, g_hlo);
    cudaGetSymbolAddress((void**)&mhi, g_mhi);
    cudaGetSymbolAddress((void**)&mlo, g_mlo);
    cudaGetSymbolAddress((void**)&Wthi, g_Wthi);
    cudaGetSymbolAddress((void**)&Wtlo, g_Wtlo);
    cudaGetSymbolAddress((void**)&cntA, g_cntA);
    cudaGetSymbolAddress((void**)&cntB, g_cntB);
    cudaGetSymbolAddress((void**)&rpa, g_rpa);
    cudaGetSymbolAddress((void**)&rpb, g_rpb);
    cudaGetSymbolAddress((void**)&curA, g_curA);
    cudaGetSymbolAddress((void**)&curB, g_curB);
    cudaGetSymbolAddress((void**)&cola, g_cola);
    cudaGetSymbolAddress((void**)&colb, g_colb);

    static cudaStream_t s1 = nullptr, s2 = nullptr, s3 = nullptr;
    static cudaEvent_t ev0, evPrep, evCSRa, evCSRb, evRZ0, evHM1, evRZ1, evHM2, evZ2;
    static int inited = 0;
    const int GEMM_SMEM = 4 * 128 * PITCHW * 4;
    if (!inited) {
        cudaFuncSetAttribute(k_gemm_tc<0>, cudaFuncAttributeMaxDynamicSharedMemorySize, GEMM_SMEM);
        cudaFuncSetAttribute(k_gemm_tc<1>, cudaFuncAttributeMaxDynamicSharedMemorySize, GEMM_SMEM);
        cudaStreamCreateWithFlags(&s1, cudaStreamNonBlocking);
        cudaStreamCreateWithFlags(&s2, cudaStreamNonBlocking);
        cudaStreamCreateWithFlags(&s3, cudaStreamNonBlocking);
        cudaEventCreateWithFlags(&ev0, cudaEventDisableTiming);
        cudaEventCreateWithFlags(&evPrep, cudaEventDisableTiming);
        cudaEventCreateWithFlags(&evCSRa, cudaEventDisableTiming);
        cudaEventCreateWithFlags(&evCSRb, cudaEventDisableTiming);
        cudaEventCreateWithFlags(&evRZ0, cudaEventDisableTiming);
        cudaEventCreateWithFlags(&evHM1, cudaEventDisableTiming);
        cudaEventCreateWithFlags(&evRZ1, cudaEventDisableTiming);
        cudaEventCreateWithFlags(&evHM2, cudaEventDisableTiming);
        cudaEventCreateWithFlags(&evZ2, cudaEventDisableTiming);
        inited = 1;
    }

    int eb = (E + 255) / 256;
    int aggBlocks = (N + 7) / 8;
    int gemmBlocks = (N + 127) / 128;
    int n32 = N * 32;
    int epiBlocks = (n32 + 255) / 256;

    const float4* bl0 = (const float4*)bl;
    const float4* bl1 = (const float4*)(bl + 128);
    const float4* bl2 = (const float4*)(bl + 256);
    __nv_bfloat16* Wl0h = Wthi + 0 * 16384; __nv_bfloat16* Wl0l = Wtlo + 0 * 16384;
    __nv_bfloat16* Wl1h = Wthi + 1 * 16384; __nv_bfloat16* Wl1l = Wtlo + 1 * 16384;
    __nv_bfloat16* Wl2h = Wthi + 2 * 16384; __nv_bfloat16* Wl2l = Wtlo + 2 * 16384;
    __nv_bfloat16* Wr0h = Wthi + 3 * 16384; __nv_bfloat16* Wr0l = Wtlo + 3 * 16384;
    __nv_bfloat16* Wr1h = Wthi + 4 * 16384; __nv_bfloat16* Wr1l = Wtlo + 4 * 16384;
    __nv_bfloat16* Wr2h = Wthi + 5 * 16384; __nv_bfloat16* Wr2l = Wtlo + 5 * 16384;

    // ---- fork: CSR builds on s1/s2 ----
    cudaEventRecord(ev0, 0);
    cudaStreamWaitEvent(s1, ev0, 0);
    cudaStreamWaitEvent(s2, ev0, 0);
    cudaStreamWaitEvent(s3, ev0, 0);

    cudaMemsetAsync(cntA, 0, N * sizeof(int), s1);
    k_count<<<eb, 256, 0, s1>>>(adj + E, cntA, E);
    k_scan<<<1, 1024, 0, s1>>>(cntA, rpa, N);
    cudaMemcpyAsync(curA, rpa, N * sizeof(int), cudaMemcpyDeviceToDevice, s1);
    k_fill<<<eb, 256, 0, s1>>>(adj, adj + E, curA, cola, nullptr, E);
    cudaEventRecord(evCSRa, s1);

    cudaMemsetAsync(cntB, 0, N * sizeof(int), s2);
    k_count<<<eb, 256, 0, s2>>>(adjb + E, cntB, E);
    k_scan<<<1, 1024, 0, s2>>>(cntB, rpb, N);
    cudaMemcpyAsync(curB, rpb, N * sizeof(int), cudaMemcpyDeviceToDevice, s2);
    k_fill<<<eb, 256, 0, s2>>>(adjb, adjb + E, curB, colb, perm, E);
    cudaEventRecord(evCSRb, s2);

    // ---- prep on main ----
    k_wprep<<<(6 * 16384 + 255) / 256, 256>>>(Wl, Wr, Wthi, Wtlo);
    k_prep_x<<<epiBlocks, 256>>>((const float4*)x, perm, mixr, xhi, xlo, mhi, mlo, N);
    cudaEventRecord(evPrep, 0);

    // ---- layer 0 ----
    cudaStreamWaitEvent(s3, evPrep, 0);
    k_gemm_tc<0><<<gemmBlocks, 256, GEMM_SMEM, s3>>>(xhi, xlo, Wr0h, Wr0l, R, nullptr, N);
    k_gemm_tc<0><<<gemmBlocks, 256, GEMM_SMEM, s3>>>(mhi, mlo, Wr0h, Wr0l, Z, nullptr, N);
    cudaEventRecord(evRZ0, s3);
    k_gemm_tc<1><<<gemmBlocks, 256, GEMM_SMEM>>>(xhi, xlo, Wl0h, Wl0l, nullptr, Ybf, N);
    cudaStreamWaitEvent(0, evCSRa, 0);
    cudaStreamWaitEvent(0, evCSRb, 0);
    k_gather2<<<aggBlocks, 256>>>((const uint2*)Ybf, rpa, cola, rpb, colb,
                                  (float4*)aggA, (float4*)aggB, N);
    cudaStreamWaitEvent(0, evRZ0, 0);
    k_epi<<<epiBlocks, 256>>>((const float4*)aggA, (const float4*)aggB,
                              (const float4*)Z, (const float4*)R, bl0, mixr,
                              mhi, mlo, nullptr, hhi, hlo, n32);
    cudaEventRecord(evHM1, 0);

    // ---- layer 1 ----
    cudaStreamWaitEvent(s3, evHM1, 0);
    k_gemm_tc<0><<<gemmBlocks, 256, GEMM_SMEM, s3>>>(hhi, hlo, Wr1h, Wr1l, R, nullptr, N);
    k_gemm_tc<0><<<gemmBlocks, 256, GEMM_SMEM, s3>>>(mhi, mlo, Wr1h, Wr1l, Z, nullptr, N);
    cudaEventRecord(evRZ1, s3);
    k_gemm_tc<1><<<gemmBlocks, 256, GEMM_SMEM>>>(hhi, hlo, Wl1h, Wl1l, nullptr, Ybf, N);
    k_gather2<<<aggBlocks, 256>>>((const uint2*)Ybf, rpa, cola, rpb, colb,
                                  (float4*)aggA, (float4*)aggB, N);
    cudaStreamWaitEvent(0, evRZ1, 0);
    k_epi<<<epiBlocks, 256>>>((const float4*)aggA, (const float4*)aggB,
                              (const float4*)Z, (const float4*)R, bl1, mixr,
                              mhi, mlo, nullptr, hhi, hlo, n32);
    cudaEventRecord(evHM2, 0);

    // ---- layer 2 (no h chain) ----
    cudaStreamWaitEvent(s3, evHM2, 0);
    k_gemm_tc<0><<<gemmBlocks, 256, GEMM_SMEM, s3>>>(mhi, mlo, Wr2h, Wr2l, Z, nullptr, N);
    cudaEventRecord(evZ2, s3);
    k_gemm_tc<1><<<gemmBlocks, 256, GEMM_SMEM>>>(hhi, hlo, Wl2h, Wl2l, nullptr, Ybf, N);
    k_gather2<<<aggBlocks, 256>>>((const uint2*)Ybf, rpa, cola, rpb, colb,
                                  (float4*)aggA, (float4*)aggB, N);
    cudaStreamWaitEvent(0, evZ2, 0);
    k_epi<<<epiBlocks, 256>>>((const float4*)aggA, (const float4*)aggB,
                              (const float4*)Z, nullptr, bl2, mixr,
                              nullptr, nullptr, (float4*)mixF, nullptr, nullptr, n32);

    // ---- logits ----
    k_logits<<<(N + 63) / 64, 256>>>(mixF, Wo, bo, (float*)d_out, N);
}

// round 6
// speedup vs baseline: 3.0351x; 1.1207x over previous
#include <cuda_runtime.h>
#include <cuda_bf16.h>
#include <cstdint>

#define NN 100000
#define EE 1600000

// ---------------- scratch ----------------
__device__ __align__(16) __nv_bfloat16 g_Ybf[NN * 128];
__device__ __align__(16) float g_R[NN * 128];
__device__ __align__(16) float g_Z[NN * 128];
__device__ __align__(16) float g_mixF[NN * 128];
__device__ __align__(16) __nv_bfloat16 g_xhi[NN * 128];
__device__ __align__(16) __nv_bfloat16 g_xlo[NN * 128];
__device__ __align__(16) __nv_bfloat16 g_hhi[NN * 128];
__device__ __align__(16) __nv_bfloat16 g_hlo[NN * 128];
__device__ __align__(16) __nv_bfloat16 g_mhi[NN * 128];
__device__ __align__(16) __nv_bfloat16 g_mlo[NN * 128];
__device__ __align__(16) __nv_bfloat16 g_Wthi[6 * 128 * 128];
__device__ __align__(16) __nv_bfloat16 g_Wtlo[6 * 128 * 128];

__device__ int g_cntA[NN];
__device__ int g_cntB[NN];
__device__ int g_rpa[NN + 1];
__device__ int g_rpb[NN + 1];
__device__ int g_curA[NN];
__device__ int g_curB[NN];
__device__ int g_cola[EE];
__device__ int g_colb[EE];

// ---------------- helpers ----------------
__device__ __forceinline__ uint32_t pack_bf2(__nv_bfloat16 a, __nv_bfloat16 b) {
    __nv_bfloat162 t = __halves2bfloat162(a, b);
    return *reinterpret_cast<uint32_t*>(&t);
}

__device__ __forceinline__ void split_store4(float4 v, __nv_bfloat16* hi,
                                             __nv_bfloat16* lo, int off) {
    __nv_bfloat16 hx = __float2bfloat16(v.x);
    __nv_bfloat16 hy = __float2bfloat16(v.y);
    __nv_bfloat16 hz = __float2bfloat16(v.z);
    __nv_bfloat16 hw = __float2bfloat16(v.w);
    uint2 hv, lv;
    hv.x = pack_bf2(hx, hy);
    hv.y = pack_bf2(hz, hw);
    lv.x = pack_bf2(__float2bfloat16(v.x - __bfloat162float(hx)),
                    __float2bfloat16(v.y - __bfloat162float(hy)));
    lv.y = pack_bf2(__float2bfloat16(v.z - __bfloat162float(hz)),
                    __float2bfloat16(v.w - __bfloat162float(hw)));
    *reinterpret_cast<uint2*>(hi + off) = hv;
    *reinterpret_cast<uint2*>(lo + off) = lv;
}

__device__ __forceinline__ void mma_bf16(float* c, const uint32_t* a,
                                         uint32_t b0, uint32_t b1) {
    asm volatile(
        "mma.sync.aligned.m16n8k16.row.col.f32.bf16.bf16.f32 "
        "{%0,%1,%2,%3}, {%4,%5,%6,%7}, {%8,%9}, {%0,%1,%2,%3};"
        : "+f"(c[0]), "+f"(c[1]), "+f"(c[2]), "+f"(c[3])
        : "r"(a[0]), "r"(a[1]), "r"(a[2]), "r"(a[3]), "r"(b0), "r"(b1));
}

// ---------------- CSR build ----------------
__global__ void k_count(const int* __restrict__ dst, int* __restrict__ cnt, int E) {
    int i = blockIdx.x * blockDim.x + threadIdx.x;
    if (i < E) atomicAdd(&cnt[dst[i]], 1);
}

__global__ void k_scan(const int* __restrict__ cnt, int* __restrict__ rowptr, int n) {
    __shared__ int part[1024];
    int tid = threadIdx.x;
    int chunk = (n + 1023) >> 10;
    int s0 = tid * chunk;
    int s1 = min(s0 + chunk, n);
    int s = 0;
    for (int i = s0; i < s1; i++) s += cnt[i];
    part[tid] = s;
    __syncthreads();
    for (int off = 1; off < 1024; off <<= 1) {
        int v = part[tid];
        int u = (tid >= off) ? part[tid - off] : 0;
        __syncthreads();
        part[tid] = v + u;
        __syncthreads();
    }
    int run = (tid == 0) ? 0 : part[tid - 1];
    for (int i = s0; i < s1; i++) { rowptr[i] = run; run += cnt[i]; }
    if (tid == 1023) rowptr[n] = part[1023];
}

__global__ void k_fill(const int* __restrict__ src, const int* __restrict__ dst,
                       int* __restrict__ cursor, int* __restrict__ col,
                       const int* __restrict__ perm, int E) {
    int i = blockIdx.x * blockDim.x + threadIdx.x;
    if (i < E) {
        int d = dst[i];
        int pos = atomicAdd(&cursor[d], 1);
        int s = src[i];
        col[pos] = perm ? perm[s] : s;
    }
}

// ---------------- weight prep: transpose + bf16 split ----------------
__global__ void k_wprep(const float* __restrict__ Wl, const float* __restrict__ Wr,
                        __nv_bfloat16* __restrict__ Wthi, __nv_bfloat16* __restrict__ Wtlo) {
    int i = blockIdx.x * blockDim.x + threadIdx.x;
    if (i >= 6 * 16384) return;
    int m = i >> 14;
    int r = (i >> 7) & 127;
    int c = i & 127;
    const float* W = (m < 3) ? (Wl + m * 16384) : (Wr + (m - 3) * 16384);
    float v = W[r * 128 + c];
    __nv_bfloat16 h = __float2bfloat16(v);
    Wthi[m * 16384 + c * 128 + r] = h;
    Wtlo[m * 16384 + c * 128 + r] = __float2bfloat16(v - __bfloat162float(h));
}

// ---------------- x prep: split + mixup init in one pass ----------------
__global__ void k_prep_x(const float4* __restrict__ x, const int* __restrict__ perm,
                         const float* __restrict__ mixr,
                         __nv_bfloat16* __restrict__ xhi, __nv_bfloat16* __restrict__ xlo,
                         __nv_bfloat16* __restrict__ mhi, __nv_bfloat16* __restrict__ mlo,
                         int n) {
    int idx = blockIdx.x * blockDim.x + threadIdx.x;
    if (idx >= n * 32) return;
    int row = idx >> 5, lane = idx & 31;
    float4 a = __ldg(&x[idx]);
    split_store4(a, xhi, xlo, idx * 4);
    int p = __ldg(&perm[row]);
    float r = __ldg(mixr);
    float q = 1.0f - r;
    float4 b = __ldg(&x[p * 32 + lane]);
    float4 v = make_float4(r * a.x + q * b.x, r * a.y + q * b.y,
                           r * a.z + q * b.z, r * a.w + q * b.w);
    split_store4(v, mhi, mlo, idx * 4);
}

// ---------------- tensor-core GEMM (bf16x3), fp32 or bf16 output ----------------
#define PITCHW 36
template <int BFOUT>
__global__ __launch_bounds__(256) void k_gemm_tc(
    const __nv_bfloat16* __restrict__ Ahi, const __nv_bfloat16* __restrict__ Alo,
    const __nv_bfloat16* __restrict__ Wthi, const __nv_bfloat16* __restrict__ Wtlo,
    float* __restrict__ out, __nv_bfloat16* __restrict__ outbf, int M) {
    extern __shared__ uint32_t sm[];
    uint32_t* sWh = sm;
    uint32_t* sWl = sm + 128 * PITCHW;
    uint32_t* sAh = sm + 2 * 128 * PITCHW;
    uint32_t* sAl = sm + 3 * 128 * PITCHW;
    int tid = threadIdx.x;
    int w = tid >> 5, lane = tid & 31;
    int g = lane >> 2, tg = lane & 3;
    int m0 = (w & 3) * 32;
    int n0 = (w >> 2) * 64;
    int row0 = blockIdx.x * 128;

    float acc[2][8][4];
#pragma unroll
    for (int mi = 0; mi < 2; mi++)
#pragma unroll
        for (int j = 0; j < 8; j++)
#pragma unroll
            for (int q = 0; q < 4; q++) acc[mi][j][q] = 0.f;

    for (int kc = 0; kc < 2; kc++) {
        int k0 = kc * 64;
        if (kc) __syncthreads();
#pragma unroll
        for (int j = 0; j < 4; j++) {
            int f = tid + j * 256;
            int r = f >> 3, q = f & 7;
            size_t goff = (size_t)r * 256 + k0 * 2 + q * 16;
            uint4 wh = *(const uint4*)((const char*)Wthi + goff);
            uint4 wl = *(const uint4*)((const char*)Wtlo + goff);
            *(uint4*)&sWh[r * PITCHW + q * 4] = wh;
            *(uint4*)&sWl[r * PITCHW + q * 4] = wl;
            int rg = row0 + r;
            uint4 ah = make_uint4(0, 0, 0, 0), al = make_uint4(0, 0, 0, 0);
            if (rg < M) {
                size_t aoff = (size_t)rg * 256 + k0 * 2 + q * 16;
                ah = *(const uint4*)((const char*)Ahi + aoff);
                al = *(const uint4*)((const char*)Alo + aoff);
            }
            *(uint4*)&sAh[r * PITCHW + q * 4] = ah;
            *(uint4*)&sAl[r * PITCHW + q * 4] = al;
        }
        __syncthreads();
#pragma unroll
        for (int kb = 0; kb < 4; kb++) {
            int pa = kb * 8 + tg;
            uint32_t ah[2][4], al_[2][4];
#pragma unroll
            for (int mi = 0; mi < 2; mi++) {
                int rb = (m0 + mi * 16 + g) * PITCHW;
                ah[mi][0] = sAh[rb + pa];
                ah[mi][1] = sAh[rb + 8 * PITCHW + pa];
                ah[mi][2] = sAh[rb + pa + 4];
                ah[mi][3] = sAh[rb + 8 * PITCHW + pa + 4];
                al_[mi][0] = sAl[rb + pa];
                al_[mi][1] = sAl[rb + 8 * PITCHW + pa];
                al_[mi][2] = sAl[rb + pa + 4];
                al_[mi][3] = sAl[rb + 8 * PITCHW + pa + 4];
            }
#pragma unroll
            for (int j = 0; j < 8; j++) {
                int nb = (n0 + j * 8 + g) * PITCHW;
                uint32_t bh0 = sWh[nb + pa], bh1 = sWh[nb + pa + 4];
                uint32_t bl0 = sWl[nb + pa], bl1 = sWl[nb + pa + 4];
#pragma unroll
                for (int mi = 0; mi < 2; mi++) {
                    mma_bf16(acc[mi][j], ah[mi], bh0, bh1);
                    mma_bf16(acc[mi][j], ah[mi], bl0, bl1);
                    mma_bf16(acc[mi][j], al_[mi], bh0, bh1);
                }
            }
        }
    }
#pragma unroll
    for (int mi = 0; mi < 2; mi++) {
        int r1 = row0 + m0 + mi * 16 + g;
        int r2 = r1 + 8;
#pragma unroll
        for (int j = 0; j < 8; j++) {
            int cidx = n0 + j * 8 + 2 * tg;
            if (BFOUT) {
                if (r1 < M)
                    *(__nv_bfloat162*)(outbf + (size_t)r1 * 128 + cidx) =
                        __floats2bfloat162_rn(acc[mi][j][0], acc[mi][j][1]);
                if (r2 < M)
                    *(__nv_bfloat162*)(outbf + (size_t)r2 * 128 + cidx) =
                        __floats2bfloat162_rn(acc[mi][j][2], acc[mi][j][3]);
            } else {
                if (r1 < M)
                    *(float2*)(out + (size_t)r1 * 128 + cidx) = make_float2(acc[mi][j][0], acc[mi][j][1]);
                if (r2 < M)
                    *(float2*)(out + (size_t)r2 * 128 + cidx) = make_float2(acc[mi][j][2], acc[mi][j][3]);
            }
        }
    }
}

// ---------------- gather helper (bf16 Y rows) ----------------
__device__ __forceinline__ float4 gather_mean_bf(const uint2* __restrict__ Y,
                                                 const int* __restrict__ rp,
                                                 const int* __restrict__ col,
                                                 int w, int lane) {
    int s = __ldg(&rp[w]), e = __ldg(&rp[w + 1]);
    float ax = 0.f, ay = 0.f, az = 0.f, aw = 0.f;
    int i = s;
    for (; i + 3 < e; i += 4) {
        int c0 = __ldg(&col[i + 0]);
        int c1 = __ldg(&col[i + 1]);
        int c2 = __ldg(&col[i + 2]);
        int c3 = __ldg(&col[i + 3]);
        uint2 u0 = __ldg(&Y[c0 * 32 + lane]);
        uint2 u1 = __ldg(&Y[c1 * 32 + lane]);
        uint2 u2 = __ldg(&Y[c2 * 32 + lane]);
        uint2 u3 = __ldg(&Y[c3 * 32 + lane]);
        float2 a0 = __bfloat1622float2(*(__nv_bfloat162*)&u0.x);
        float2 b0 = __bfloat1622float2(*(__nv_bfloat162*)&u0.y);
        float2 a1 = __bfloat1622float2(*(__nv_bfloat162*)&u1.x);
        float2 b1 = __bfloat1622float2(*(__nv_bfloat162*)&u1.y);
        float2 a2 = __bfloat1622float2(*(__nv_bfloat162*)&u2.x);
        float2 b2 = __bfloat1622float2(*(__nv_bfloat162*)&u2.y);
        float2 a3 = __bfloat1622float2(*(__nv_bfloat162*)&u3.x);
        float2 b3 = __bfloat1622float2(*(__nv_bfloat162*)&u3.y);
        ax += (a0.x + a1.x) + (a2.x + a3.x);
        ay += (a0.y + a1.y) + (a2.y + a3.y);
        az += (b0.x + b1.x) + (b2.x + b3.x);
        aw += (b0.y + b1.y) + (b2.y + b3.y);
    }
    for (; i < e; i++) {
        int c0 = __ldg(&col[i]);
        uint2 u0 = __ldg(&Y[c0 * 32 + lane]);
        float2 a0 = __bfloat1622float2(*(__nv_bfloat162*)&u0.x);
        float2 b0 = __bfloat1622float2(*(__nv_bfloat162*)&u0.y);
        ax += a0.x; ay += a0.y; az += b0.x; aw += b0.y;
    }
    float inv = 1.0f / (float)max(e - s, 1);
    return make_float4(ax * inv, ay * inv, az * inv, aw * inv);
}

// ---------------- fused: dual gather + mixup epilogue (no agg round-trip) ----------------
__global__ void k_gatherepi(const uint2* __restrict__ Y,
                            const int* __restrict__ rpa, const int* __restrict__ cola,
                            const int* __restrict__ rpb, const int* __restrict__ colb,
                            const float4* __restrict__ Z, const float4* __restrict__ R,
                            const float4* __restrict__ bias, const float* __restrict__ mixr,
                            __nv_bfloat16* __restrict__ mhi, __nv_bfloat16* __restrict__ mlo,
                            float4* __restrict__ mixF,
                            __nv_bfloat16* __restrict__ hhi, __nv_bfloat16* __restrict__ hlo,
                            int n) {
    int w = (blockIdx.x * blockDim.x + threadIdx.x) >> 5;
    int lane = threadIdx.x & 31;
    if (w >= n) return;
    float4 aA = gather_mean_bf(Y, rpa, cola, w, lane);
    float4 aB = gather_mean_bf(Y, rpb, colb, w, lane);
    int idx = w * 32 + lane;
    float4 z = __ldg(&Z[idx]);
    float4 b = __ldg(&bias[lane]);
    float r = __ldg(mixr);
    float q = 1.0f - r;
    float4 sA = make_float4(fmaxf(aA.x + z.x + b.x, 0.f), fmaxf(aA.y + z.y + b.y, 0.f),
                            fmaxf(aA.z + z.z + b.z, 0.f), fmaxf(aA.w + z.w + b.w, 0.f));
    float4 sB = make_float4(fmaxf(aB.x + z.x + b.x, 0.f), fmaxf(aB.y + z.y + b.y, 0.f),
                            fmaxf(aB.z + z.z + b.z, 0.f), fmaxf(aB.w + z.w + b.w, 0.f));
    float4 mix = make_float4(r * sA.x + q * sB.x, r * sA.y + q * sB.y,
                             r * sA.z + q * sB.z, r * sA.w + q * sB.w);
    if (mixF) mixF[idx] = mix;
    else split_store4(mix, mhi, mlo, idx * 4);
    if (hhi) {
        float4 rv = __ldg(&R[idx]);
        float4 h = make_float4(
            fmaxf(aA.x + rv.x + b.x, 0.f), fmaxf(aA.y + rv.y + b.y, 0.f),
            fmaxf(aA.z + rv.z + b.z, 0.f), fmaxf(aA.w + rv.w + b.w, 0.f));
        split_store4(h, hhi, hlo, idx * 4);
    }
}

// ---------------- logits + log_softmax ----------------
__global__ __launch_bounds__(256) void k_logits(
    const float* __restrict__ X, const float* __restrict__ Wo,
    const float* __restrict__ bo, float* __restrict__ out, int n) {
    __shared__ float Ws[128 * 40];
    __shared__ float bs[40];
    int tid = threadIdx.x;
    for (int i = tid; i < 128 * 40; i += 256) Ws[i] = Wo[i];
    if (tid < 40) bs[tid] = bo[tid];
    __syncthreads();

    int row = blockIdx.x * 64 + (tid >> 2);
    int row_c = min(row, n - 1);
    int cg = (tid & 3) * 10;

    float acc[10];
#pragma unroll
    for (int j = 0; j < 10; j++) acc[j] = bs[cg + j];

    const float4* xr = (const float4*)(X + (size_t)row_c * 128);
#pragma unroll 8
    for (int k4 = 0; k4 < 32; k4++) {
        float4 xv = __ldg(&xr[k4]);
        float xs[4] = { xv.x, xv.y, xv.z, xv.w };
#pragma unroll
        for (int kk = 0; kk < 4; kk++) {
            int k = k4 * 4 + kk;
#pragma unroll
            for (int j = 0; j < 10; j++)
                acc[j] = fmaf(xs[kk], Ws[k * 40 + cg + j], acc[j]);
        }
    }
    float m = acc[0];
#pragma unroll
    for (int j = 1; j < 10; j++) m = fmaxf(m, acc[j]);
    m = fmaxf(m, __shfl_xor_sync(0xffffffffu, m, 1));
    m = fmaxf(m, __shfl_xor_sync(0xffffffffu, m, 2));
    float s = 0.f;
#pragma unroll
    for (int j = 0; j < 10; j++) s += expf(acc[j] - m);
    s += __shfl_xor_sync(0xffffffffu, s, 1);
    s += __shfl_xor_sync(0xffffffffu, s, 2);
    float lse = m + logf(s);
    if (row < n) {
#pragma unroll
        for (int j = 0; j < 10; j++) out[row * 40 + cg + j] = acc[j] - lse;
    }
}

// ---------------- launch ----------------
extern "C" void kernel_launch(void* const* d_in, const int* in_sizes, int n_in,
                              void* d_out, int out_size) {
    const float* x    = (const float*)d_in[0];
    const float* Wl   = (const float*)d_in[1];
    const float* bl   = (const float*)d_in[2];
    const float* Wr   = (const float*)d_in[3];
    const float* Wo   = (const float*)d_in[4];
    const float* bo   = (const float*)d_in[5];
    const float* mixr = (const float*)d_in[6];
    const int*   adj  = (const int*)d_in[7];
    const int*   adjb = (const int*)d_in[8];
    const int*   perm = (const int*)d_in[9];

    int N = in_sizes[0] / 128;
    int E = in_sizes[7] / 2;

    float *R, *Z, *mixF;
    __nv_bfloat16 *Ybf, *xhi, *xlo, *hhi, *hlo, *mhi, *mlo, *Wthi, *Wtlo;
    int *cntA, *cntB, *rpa, *rpb, *curA, *curB, *cola, *colb;
    cudaGetSymbolAddress((void**)&Ybf, g_Ybf);
    cudaGetSymbolAddress((void**)&R, g_R);
    cudaGetSymbolAddress((void**)&Z, g_Z);
    cudaGetSymbolAddress((void**)&mixF, g_mixF);
    cudaGetSymbolAddress((void**)&xhi, g_xhi);
    cudaGetSymbolAddress((void**)&xlo, g_xlo);
    cudaGetSymbolAddress((void**)&hhi, g_hhi);
    cudaGetSymbolAddress((void**)&hlo, g_hlo);
    cudaGetSymbolAddress((void**)&mhi, g_mhi);
    cudaGetSymbolAddress((void**)&mlo, g_mlo);
    cudaGetSymbolAddress((void**)&Wthi, g_Wthi);
    cudaGetSymbolAddress((void**)&Wtlo, g_Wtlo);
    cudaGetSymbolAddress((void**)&cntA, g_cntA);
    cudaGetSymbolAddress((void**)&cntB, g_cntB);
    cudaGetSymbolAddress((void**)&rpa, g_rpa);
    cudaGetSymbolAddress((void**)&rpb, g_rpb);
    cudaGetSymbolAddress((void**)&curA, g_curA);
    cudaGetSymbolAddress((void**)&curB, g_curB);
    cudaGetSymbolAddress((void**)&cola, g_cola);
    cudaGetSymbolAddress((void**)&colb, g_colb);

    static cudaStream_t s1 = nullptr, s2 = nullptr, s3 = nullptr;
    static cudaEvent_t ev0, evPrep, evCSRa, evCSRb, evRZ0, evHM1, evRZ1, evHM2, evZ2;
    static int inited = 0;
    const int GEMM_SMEM = 4 * 128 * PITCHW * 4;
    if (!inited) {
        cudaFuncSetAttribute(k_gemm_tc<0>, cudaFuncAttributeMaxDynamicSharedMemorySize, GEMM_SMEM);
        cudaFuncSetAttribute(k_gemm_tc<1>, cudaFuncAttributeMaxDynamicSharedMemorySize, GEMM_SMEM);
        cudaStreamCreateWithFlags(&s1, cudaStreamNonBlocking);
        cudaStreamCreateWithFlags(&s2, cudaStreamNonBlocking);
        cudaStreamCreateWithFlags(&s3, cudaStreamNonBlocking);
        cudaEventCreateWithFlags(&ev0, cudaEventDisableTiming);
        cudaEventCreateWithFlags(&evPrep, cudaEventDisableTiming);
        cudaEventCreateWithFlags(&evCSRa, cudaEventDisableTiming);
        cudaEventCreateWithFlags(&evCSRb, cudaEventDisableTiming);
        cudaEventCreateWithFlags(&evRZ0, cudaEventDisableTiming);
        cudaEventCreateWithFlags(&evHM1, cudaEventDisableTiming);
        cudaEventCreateWithFlags(&evRZ1, cudaEventDisableTiming);
        cudaEventCreateWithFlags(&evHM2, cudaEventDisableTiming);
        cudaEventCreateWithFlags(&evZ2, cudaEventDisableTiming);
        inited = 1;
    }

    int eb = (E + 255) / 256;
    int aggBlocks = (N + 7) / 8;
    int gemmBlocks = (N + 127) / 128;
    int n32 = N * 32;
    int epiBlocks = (n32 + 255) / 256;

    const float4* bl0 = (const float4*)bl;
    const float4* bl1 = (const float4*)(bl + 128);
    const float4* bl2 = (const float4*)(bl + 256);
    __nv_bfloat16* Wl0h = Wthi + 0 * 16384; __nv_bfloat16* Wl0l = Wtlo + 0 * 16384;
    __nv_bfloat16* Wl1h = Wthi + 1 * 16384; __nv_bfloat16* Wl1l = Wtlo + 1 * 16384;
    __nv_bfloat16* Wl2h = Wthi + 2 * 16384; __nv_bfloat16* Wl2l = Wtlo + 2 * 16384;
    __nv_bfloat16* Wr0h = Wthi + 3 * 16384; __nv_bfloat16* Wr0l = Wtlo + 3 * 16384;
    __nv_bfloat16* Wr1h = Wthi + 4 * 16384; __nv_bfloat16* Wr1l = Wtlo + 4 * 16384;
    __nv_bfloat16* Wr2h = Wthi + 5 * 16384; __nv_bfloat16* Wr2l = Wtlo + 5 * 16384;

    // ---- fork: CSR builds on s1/s2 ----
    cudaEventRecord(ev0, 0);
    cudaStreamWaitEvent(s1, ev0, 0);
    cudaStreamWaitEvent(s2, ev0, 0);
    cudaStreamWaitEvent(s3, ev0, 0);

    cudaMemsetAsync(cntA, 0, N * sizeof(int), s1);
    k_count<<<eb, 256, 0, s1>>>(adj + E, cntA, E);
    k_scan<<<1, 1024, 0, s1>>>(cntA, rpa, N);
    cudaMemcpyAsync(curA, rpa, N * sizeof(int), cudaMemcpyDeviceToDevice, s1);
    k_fill<<<eb, 256, 0, s1>>>(adj, adj + E, curA, cola, nullptr, E);
    cudaEventRecord(evCSRa, s1);

    cudaMemsetAsync(cntB, 0, N * sizeof(int), s2);
    k_count<<<eb, 256, 0, s2>>>(adjb + E, cntB, E);
    k_scan<<<1, 1024, 0, s2>>>(cntB, rpb, N);
    cudaMemcpyAsync(curB, rpb, N * sizeof(int), cudaMemcpyDeviceToDevice, s2);
    k_fill<<<eb, 256, 0, s2>>>(adjb, adjb + E, curB, colb, perm, E);
    cudaEventRecord(evCSRb, s2);

    // ---- prep on main ----
    k_wprep<<<(6 * 16384 + 255) / 256, 256>>>(Wl, Wr, Wthi, Wtlo);
    k_prep_x<<<epiBlocks, 256>>>((const float4*)x, perm, mixr, xhi, xlo, mhi, mlo, N);
    cudaEventRecord(evPrep, 0);

    // ---- layer 0 ----
    cudaStreamWaitEvent(s3, evPrep, 0);
    k_gemm_tc<0><<<gemmBlocks, 256, GEMM_SMEM, s3>>>(xhi, xlo, Wr0h, Wr0l, R, nullptr, N);
    k_gemm_tc<0><<<gemmBlocks, 256, GEMM_SMEM, s3>>>(mhi, mlo, Wr0h, Wr0l, Z, nullptr, N);
    cudaEventRecord(evRZ0, s3);
    k_gemm_tc<1><<<gemmBlocks, 256, GEMM_SMEM>>>(xhi, xlo, Wl0h, Wl0l, nullptr, Ybf, N);
    cudaStreamWaitEvent(0, evCSRa, 0);
    cudaStreamWaitEvent(0, evCSRb, 0);
    cudaStreamWaitEvent(0, evRZ0, 0);
    k_gatherepi<<<aggBlocks, 256>>>((const uint2*)Ybf, rpa, cola, rpb, colb,
                                    (const float4*)Z, (const float4*)R, bl0, mixr,
                                    mhi, mlo, nullptr, hhi, hlo, N);
    cudaEventRecord(evHM1, 0);

    // ---- layer 1 ----
    cudaStreamWaitEvent(s3, evHM1, 0);
    k_gemm_tc<0><<<gemmBlocks, 256, GEMM_SMEM, s3>>>(hhi, hlo, Wr1h, Wr1l, R, nullptr, N);
    k_gemm_tc<0><<<gemmBlocks, 256, GEMM_SMEM, s3>>>(mhi, mlo, Wr1h, Wr1l, Z, nullptr, N);
    cudaEventRecord(evRZ1, s3);
    k_gemm_tc<1><<<gemmBlocks, 256, GEMM_SMEM>>>(hhi, hlo, Wl1h, Wl1l, nullptr, Ybf, N);
    cudaStreamWaitEvent(0, evRZ1, 0);
    k_gatherepi<<<aggBlocks, 256>>>((const uint2*)Ybf, rpa, cola, rpb, colb,
                                    (const float4*)Z, (const float4*)R, bl1, mixr,
                                    mhi, mlo, nullptr, hhi, hlo, N);
    cudaEventRecord(evHM2, 0);

    // ---- layer 2 (no h chain) ----
    cudaStreamWaitEvent(s3, evHM2, 0);
    k_gemm_tc<0><<<gemmBlocks, 256, GEMM_SMEM, s3>>>(mhi, mlo, Wr2h, Wr2l, Z, nullptr, N);
    cudaEventRecord(evZ2, s3);
    k_gemm_tc<1><<<gemmBlocks, 256, GEMM_SMEM>>>(hhi, hlo, Wl2h, Wl2l, nullptr, Ybf, N);
    cudaStreamWaitEvent(0, evZ2, 0);
    k_gatherepi<<<aggBlocks, 256>>>((const uint2*)Ybf, rpa, cola, rpb, colb,
                                    (const float4*)Z, nullptr, bl2, mixr,
                                    nullptr, nullptr, (float4*)mixF, nullptr, nullptr, N);

    // ---- logits ----
    k_logits<<<(N + 63) / 64, 256>>>(mixF, Wo, bo, (float*)d_out, N);
}